// round 11
// baseline (speedup 1.0000x reference)
#include <cuda_runtime.h>
#include <cuda_bf16.h>
#include <stdint.h>

// Problem dims (fixed by the reference)
#define B_  8
#define N_  2048
#define H_  128
#define R_  (B_ * N_)   // 16384 total rows

// GEMM tiling
#define BM 128
#define BN 128
#define BK 32
#define KP 40           // padded K stride (bf16) for BK=32 tiles -> conflict-free
#define KP2 136         // padded K stride (bf16) for K=128 resident tiles
#define NTHREADS 256

// -------- scratch (__device__ globals: no allocation allowed) --------
__device__ float g_m2 [R_ * H_];        // 8 MB
__device__ float g_mt [B_ * H_ * N_];   // 8 MB   (m2 transposed per batch: [b][h][n])
__device__ float g_msg[R_ * H_];        // 8 MB
__device__ float g_gx [R_ * 3 * H_];    // 24 MB
__device__ float g_gh [R_ * 3 * H_];    // 24 MB

__device__ __forceinline__ uint32_t lds_u32(const __nv_bfloat16* p) {
    return *reinterpret_cast<const uint32_t*>(p);
}

__device__ __forceinline__ void mma_bf16(float* c,
                                         uint32_t a0, uint32_t a1, uint32_t a2, uint32_t a3,
                                         uint32_t b0, uint32_t b1) {
    asm volatile(
        "mma.sync.aligned.m16n8k16.row.col.f32.bf16.bf16.f32 "
        "{%0,%1,%2,%3}, {%4,%5,%6,%7}, {%8,%9}, {%0,%1,%2,%3};\n"
        : "+f"(c[0]), "+f"(c[1]), "+f"(c[2]), "+f"(c[3])
        : "r"(a0), "r"(a1), "r"(a2), "r"(a3), "r"(b0), "r"(b1));
}

// split a float4 into hi/lo bf16 and store as two bf162 pairs at smem offset `off`
__device__ __forceinline__ void split_store(__nv_bfloat16* shi, __nv_bfloat16* slo,
                                            int off, float4 v) {
    float va[4] = {v.x, v.y, v.z, v.w};
    __nv_bfloat16 hi[4], lo[4];
    #pragma unroll
    for (int q = 0; q < 4; q++) {
        hi[q] = __float2bfloat16(va[q]);
        lo[q] = __float2bfloat16(va[q] - __bfloat162float(hi[q]));
    }
    *reinterpret_cast<__nv_bfloat162*>(shi + off)     = __halves2bfloat162(hi[0], hi[1]);
    *reinterpret_cast<__nv_bfloat162*>(shi + off + 2) = __halves2bfloat162(hi[2], hi[3]);
    *reinterpret_cast<__nv_bfloat162*>(slo + off)     = __halves2bfloat162(lo[0], lo[1]);
    *reinterpret_cast<__nv_bfloat162*>(slo + off + 2) = __halves2bfloat162(lo[2], lo[3]);
}

// warp-tile MMA sweep over KC columns of hi/lo split tiles.
// A tile rows at wrow..wrow+63, B tile rows at wcol..wcol+31, stride = padded K (bf16 elems)
template<int STRIDE, int KC>
__device__ __forceinline__ void tile_mma(const __nv_bfloat16* sAhi, const __nv_bfloat16* sAlo,
                                         const __nv_bfloat16* sBhi, const __nv_bfloat16* sBlo,
                                         int wrow, int wcol, int lane,
                                         float acc[4][4][4]) {
    const int arow = lane >> 2;        // 0..7
    const int kq   = (lane & 3) * 2;   // 0,2,4,6
    #pragma unroll
    for (int kk = 0; kk < KC; kk += 16) {
        uint32_t ah[4][4], al[4][4];
        #pragma unroll
        for (int i = 0; i < 4; i++) {
            const int base = (wrow + i * 16 + arow) * STRIDE + kk + kq;
            ah[i][0] = lds_u32(sAhi + base);
            ah[i][1] = lds_u32(sAhi + base + 8 * STRIDE);
            ah[i][2] = lds_u32(sAhi + base + 8);
            ah[i][3] = lds_u32(sAhi + base + 8 * STRIDE + 8);
            al[i][0] = lds_u32(sAlo + base);
            al[i][1] = lds_u32(sAlo + base + 8 * STRIDE);
            al[i][2] = lds_u32(sAlo + base + 8);
            al[i][3] = lds_u32(sAlo + base + 8 * STRIDE + 8);
        }
        uint32_t bh[4][2], bl[4][2];
        #pragma unroll
        for (int j = 0; j < 4; j++) {
            const int base = (wcol + j * 8 + arow) * STRIDE + kk + kq;
            bh[j][0] = lds_u32(sBhi + base);
            bh[j][1] = lds_u32(sBhi + base + 8);
            bl[j][0] = lds_u32(sBlo + base);
            bl[j][1] = lds_u32(sBlo + base + 8);
        }
        #pragma unroll
        for (int i = 0; i < 4; i++)
            #pragma unroll
            for (int j = 0; j < 4; j++) {
                mma_bf16(acc[i][j], ah[i][0], ah[i][1], ah[i][2], ah[i][3], bh[j][0], bh[j][1]);
                mma_bf16(acc[i][j], ah[i][0], ah[i][1], ah[i][2], ah[i][3], bl[j][0], bl[j][1]);
                mma_bf16(acc[i][j], al[i][0], al[i][1], al[i][2], al[i][3], bh[j][0], bh[j][1]);
            }
    }
}

// C[M x N] = act( A[M x K] * B[N x K]^T + bias ), fp32 in/out.
// 2-term bf16 split per operand, 3 bf16 MMAs (hi*hi + hi*lo + lo*hi), fp32 accumulate.
// Software-pipelined: next k-tile LDGs issue before the MMA sweep of the current tile.
template<int ACT>
__global__ void __launch_bounds__(NTHREADS, 1)
gemm_nt_split(const float* __restrict__ A, long long strideA, int lda,
              const float* __restrict__ Bm, long long strideB, int ldb,
              const float* __restrict__ bias,
              float* __restrict__ C, long long strideC, int ldc,
              int K)
{
    __shared__ __nv_bfloat16 sAhi[BM * KP];
    __shared__ __nv_bfloat16 sAlo[BM * KP];
    __shared__ __nv_bfloat16 sBhi[BN * KP];
    __shared__ __nv_bfloat16 sBlo[BN * KP];

    const int tid  = threadIdx.x;
    const int lane = tid & 31;
    const int warp = tid >> 5;
    const int wrow = (warp >> 2) * 64;
    const int wcol = (warp & 3) * 32;

    const long long bz = blockIdx.z;
    const float* Ag = A  + bz * strideA + (long long)blockIdx.y * BM * lda;
    const float* Bg = Bm + bz * strideB + (long long)blockIdx.x * BN * ldb;

    const int lr = tid >> 3;         // row 0..31 (+32p)
    const int lc = (tid & 7) * 4;    // float col 0..28

    float acc[4][4][4];
    #pragma unroll
    for (int i = 0; i < 4; i++)
        #pragma unroll
        for (int j = 0; j < 4; j++)
            #pragma unroll
            for (int t = 0; t < 4; t++) acc[i][j][t] = 0.f;

    // prologue: load first k-tile into registers
    float4 ra[4], rb[4];
    #pragma unroll
    for (int p = 0; p < 4; p++) {
        ra[p] = *reinterpret_cast<const float4*>(Ag + (long long)(lr + 32 * p) * lda + lc);
        rb[p] = *reinterpret_cast<const float4*>(Bg + (long long)(lr + 32 * p) * ldb + lc);
    }

    for (int k0 = 0; k0 < K; k0 += BK) {
        __syncthreads();   // previous iteration's MMA readers done with smem
        #pragma unroll
        for (int p = 0; p < 4; p++) {
            const int off = (lr + 32 * p) * KP + lc;
            split_store(sAhi, sAlo, off, ra[p]);
            split_store(sBhi, sBlo, off, rb[p]);
        }
        __syncthreads();   // smem tiles ready

        // prefetch next k-tile: LDGs in flight while the MMA sweep runs
        const bool more = (k0 + BK) < K;
        float4 na[4], nb[4];
        if (more) {
            #pragma unroll
            for (int p = 0; p < 4; p++) {
                na[p] = *reinterpret_cast<const float4*>(Ag + (long long)(lr + 32 * p) * lda + (k0 + BK + lc));
                nb[p] = *reinterpret_cast<const float4*>(Bg + (long long)(lr + 32 * p) * ldb + (k0 + BK + lc));
            }
        }

        tile_mma<KP, BK>(sAhi, sAlo, sBhi, sBlo, wrow, wcol, lane, acc);

        if (more) {
            #pragma unroll
            for (int p = 0; p < 4; p++) { ra[p] = na[p]; rb[p] = nb[p]; }
        }
    }

    // epilogue: bias + optional relu, fp32 store
    float* Cg = C + bz * strideC;
    const int rb0 = blockIdx.y * BM + wrow;
    const int cb0 = blockIdx.x * BN + wcol;
    #pragma unroll
    for (int i = 0; i < 4; i++) {
        const int r0 = rb0 + i * 16 + (lane >> 2);
        #pragma unroll
        for (int j = 0; j < 4; j++) {
            const int c0 = cb0 + j * 8 + (lane & 3) * 2;
            float v0 = acc[i][j][0], v1 = acc[i][j][1], v2 = acc[i][j][2], v3 = acc[i][j][3];
            if (bias) {
                const float bb0 = bias[c0], bb1 = bias[c0 + 1];
                v0 += bb0; v1 += bb1; v2 += bb0; v3 += bb1;
            }
            if (ACT) {
                v0 = fmaxf(v0, 0.f); v1 = fmaxf(v1, 0.f);
                v2 = fmaxf(v2, 0.f); v3 = fmaxf(v3, 0.f);
            }
            *reinterpret_cast<float2*>(Cg + (long long)r0 * ldc + c0)       = make_float2(v0, v1);
            *reinterpret_cast<float2*>(Cg + (long long)(r0 + 8) * ldc + c0) = make_float2(v2, v3);
        }
    }
}

// -------- fused MLP: m2 = relu(relu(h W1^T + b1) W2^T + b2) --------
// One CTA per 128 rows. K=128 lives entirely in smem; m1 never touches HBM.
// Dynamic smem: 4 arrays of [128][KP2] bf16 = 139,264 bytes.
extern __shared__ __nv_bfloat16 s_dyn[];

__global__ void __launch_bounds__(NTHREADS, 1)
mlp_fused(const float* __restrict__ h,
          const float* __restrict__ W1, const float* __restrict__ b1,
          const float* __restrict__ W2, const float* __restrict__ b2,
          float* __restrict__ m2)
{
    __nv_bfloat16* sXhi = s_dyn;
    __nv_bfloat16* sXlo = sXhi + 128 * KP2;
    __nv_bfloat16* sWhi = sXlo + 128 * KP2;
    __nv_bfloat16* sWlo = sWhi + 128 * KP2;

    const int tid  = threadIdx.x;
    const int lane = tid & 31;
    const int warp = tid >> 5;
    const int wrow = (warp >> 2) * 64;
    const int wcol = (warp & 3) * 32;

    const float* Xg = h + (long long)blockIdx.x * 128 * H_;

    // load + split X (h rows) and W1: 128x128 fp32 each -> 4096 float4 each
    #pragma unroll
    for (int it = 0; it < 16; it++) {
        const int i   = tid + it * NTHREADS;      // 0..4095
        const int row = i >> 5;
        const int c4  = (i & 31) * 4;
        const int off = row * KP2 + c4;
        split_store(sXhi, sXlo, off, *reinterpret_cast<const float4*>(Xg + row * H_ + c4));
        split_store(sWhi, sWlo, off, *reinterpret_cast<const float4*>(W1 + row * H_ + c4));
    }
    __syncthreads();

    float acc[4][4][4];
    #pragma unroll
    for (int i = 0; i < 4; i++)
        #pragma unroll
        for (int j = 0; j < 4; j++)
            #pragma unroll
            for (int t = 0; t < 4; t++) acc[i][j][t] = 0.f;

    // ---- gemm1: X @ W1^T ----
    tile_mma<KP2, 128>(sXhi, sXlo, sWhi, sWlo, wrow, wcol, lane, acc);
    __syncthreads();   // all warps done reading sX / sW before overwrite

    // relu(acc + b1) -> split back into sX (becomes m1 tile)
    #pragma unroll
    for (int i = 0; i < 4; i++) {
        const int row = wrow + i * 16 + (lane >> 2);
        #pragma unroll
        for (int j = 0; j < 4; j++) {
            const int col = wcol + j * 8 + (lane & 3) * 2;
            const float bb0 = b1[col], bb1 = b1[col + 1];
            float v0 = fmaxf(acc[i][j][0] + bb0, 0.f);
            float v1 = fmaxf(acc[i][j][1] + bb1, 0.f);
            float v2 = fmaxf(acc[i][j][2] + bb0, 0.f);
            float v3 = fmaxf(acc[i][j][3] + bb1, 0.f);
            __nv_bfloat16 h0 = __float2bfloat16(v0), h1 = __float2bfloat16(v1);
            __nv_bfloat16 h2 = __float2bfloat16(v2), h3 = __float2bfloat16(v3);
            __nv_bfloat16 l0 = __float2bfloat16(v0 - __bfloat162float(h0));
            __nv_bfloat16 l1 = __float2bfloat16(v1 - __bfloat162float(h1));
            __nv_bfloat16 l2 = __float2bfloat16(v2 - __bfloat162float(h2));
            __nv_bfloat16 l3 = __float2bfloat16(v3 - __bfloat162float(h3));
            *reinterpret_cast<__nv_bfloat162*>(sXhi + row * KP2 + col)       = __halves2bfloat162(h0, h1);
            *reinterpret_cast<__nv_bfloat162*>(sXlo + row * KP2 + col)       = __halves2bfloat162(l0, l1);
            *reinterpret_cast<__nv_bfloat162*>(sXhi + (row + 8) * KP2 + col) = __halves2bfloat162(h2, h3);
            *reinterpret_cast<__nv_bfloat162*>(sXlo + (row + 8) * KP2 + col) = __halves2bfloat162(l2, l3);
            // reset acc for gemm2
            acc[i][j][0] = acc[i][j][1] = acc[i][j][2] = acc[i][j][3] = 0.f;
        }
    }

    // load + split W2 (overwrites W1 tile)
    #pragma unroll
    for (int it = 0; it < 16; it++) {
        const int i   = tid + it * NTHREADS;
        const int row = i >> 5;
        const int c4  = (i & 31) * 4;
        split_store(sWhi, sWlo, row * KP2 + c4, *reinterpret_cast<const float4*>(W2 + row * H_ + c4));
    }
    __syncthreads();

    // ---- gemm2: m1 @ W2^T ----
    tile_mma<KP2, 128>(sXhi, sXlo, sWhi, sWlo, wrow, wcol, lane, acc);

    // relu(acc + b2) -> m2 global
    float* Cg = m2 + (long long)blockIdx.x * 128 * H_;
    #pragma unroll
    for (int i = 0; i < 4; i++) {
        const int row = wrow + i * 16 + (lane >> 2);
        #pragma unroll
        for (int j = 0; j < 4; j++) {
            const int col = wcol + j * 8 + (lane & 3) * 2;
            const float bb0 = b2[col], bb1 = b2[col + 1];
            float v0 = fmaxf(acc[i][j][0] + bb0, 0.f);
            float v1 = fmaxf(acc[i][j][1] + bb1, 0.f);
            float v2 = fmaxf(acc[i][j][2] + bb0, 0.f);
            float v3 = fmaxf(acc[i][j][3] + bb1, 0.f);
            *reinterpret_cast<float2*>(Cg + (long long)row * H_ + col)       = make_float2(v0, v1);
            *reinterpret_cast<float2*>(Cg + (long long)(row + 8) * H_ + col) = make_float2(v2, v3);
        }
    }
}

// transpose m2 [b][n][h] -> mt [b][h][n]   (so the adjacency gemm is also NT)
__global__ void transpose_m(const float* __restrict__ src, float* __restrict__ dst)
{
    __shared__ float t[32][33];
    const int b  = blockIdx.z;
    const int n0 = blockIdx.x * 32;
    const int h0 = blockIdx.y * 32;
    const float* s = src + (long long)b * N_ * H_;
    float* d       = dst + (long long)b * H_ * N_;
    const int tx = threadIdx.x, ty = threadIdx.y;  // 32 x 8
    #pragma unroll
    for (int i = 0; i < 32; i += 8)
        t[ty + i][tx] = s[(long long)(n0 + ty + i) * H_ + h0 + tx];
    __syncthreads();
    #pragma unroll
    for (int i = 0; i < 32; i += 8)
        d[(long long)(h0 + ty + i) * N_ + n0 + tx] = t[tx][ty + i];
}

// GRU gate combine (torch GRUCell order r,z,n), vectorized float4
__global__ void gru_gates(const float* __restrict__ gx, const float* __restrict__ gh,
                          const float* __restrict__ h, float* __restrict__ out)
{
    const int idx4 = blockIdx.x * blockDim.x + threadIdx.x;
    if (idx4 >= R_ * H_ / 4) return;
    const int i  = idx4 >> 5;            // row
    const int j4 = (idx4 & 31) * 4;      // col
    const float* gxr = gx + (long long)i * 3 * H_;
    const float* ghr = gh + (long long)i * 3 * H_;
    const float4 xr = *reinterpret_cast<const float4*>(gxr + j4);
    const float4 xz = *reinterpret_cast<const float4*>(gxr + j4 + H_);
    const float4 xn = *reinterpret_cast<const float4*>(gxr + j4 + 2 * H_);
    const float4 hr = *reinterpret_cast<const float4*>(ghr + j4);
    const float4 hz = *reinterpret_cast<const float4*>(ghr + j4 + H_);
    const float4 hn = *reinterpret_cast<const float4*>(ghr + j4 + 2 * H_);
    const float4 hv = *reinterpret_cast<const float4*>(h + (long long)i * H_ + j4);

    float4 o;
    {
        const float r = 1.f / (1.f + expf(-(xr.x + hr.x)));
        const float z = 1.f / (1.f + expf(-(xz.x + hz.x)));
        const float n = tanhf(xn.x + r * hn.x);
        o.x = (1.f - z) * n + z * hv.x;
    }
    {
        const float r = 1.f / (1.f + expf(-(xr.y + hr.y)));
        const float z = 1.f / (1.f + expf(-(xz.y + hz.y)));
        const float n = tanhf(xn.y + r * hn.y);
        o.y = (1.f - z) * n + z * hv.y;
    }
    {
        const float r = 1.f / (1.f + expf(-(xr.z + hr.z)));
        const float z = 1.f / (1.f + expf(-(xz.z + hz.z)));
        const float n = tanhf(xn.z + r * hn.z);
        o.z = (1.f - z) * n + z * hv.z;
    }
    {
        const float r = 1.f / (1.f + expf(-(xr.w + hr.w)));
        const float z = 1.f / (1.f + expf(-(xz.w + hz.w)));
        const float n = tanhf(xn.w + r * hn.w);
        o.w = (1.f - z) * n + z * hv.w;
    }
    *reinterpret_cast<float4*>(out + (long long)i * H_ + j4) = o;
}

extern "C" void kernel_launch(void* const* d_in, const int* in_sizes, int n_in,
                              void* d_out, int out_size)
{
    const float* h   = (const float*)d_in[0];   // [8,2048,128]
    const float* A   = (const float*)d_in[1];   // [8,2048,2048]
    const float* W1  = (const float*)d_in[2];   // [128,128]
    const float* b1  = (const float*)d_in[3];   // [128]
    const float* W2  = (const float*)d_in[4];   // [128,128]
    const float* b2  = (const float*)d_in[5];   // [128]
    const float* Wih = (const float*)d_in[6];   // [384,128]
    const float* Whh = (const float*)d_in[7];   // [384,128]
    const float* bih = (const float*)d_in[8];   // [384]
    const float* bhh = (const float*)d_in[9];   // [384]
    float* out = (float*)d_out;                 // [8,2048,128]

    float *m2, *mt, *msg, *gx, *gh;
    cudaGetSymbolAddress((void**)&m2,  g_m2);
    cudaGetSymbolAddress((void**)&mt,  g_mt);
    cudaGetSymbolAddress((void**)&msg, g_msg);
    cudaGetSymbolAddress((void**)&gx,  g_gx);
    cudaGetSymbolAddress((void**)&gh,  g_gh);

    const dim3 blk(NTHREADS);
    const int MLP_SMEM = 4 * 128 * KP2 * (int)sizeof(__nv_bfloat16);  // 139264

    static bool attr_done = false;
    cudaFuncSetAttribute(mlp_fused, cudaFuncAttributeMaxDynamicSharedMemorySize, MLP_SMEM);
    (void)attr_done;

    // 1+2) fused MLP: m2 = relu(relu(h W1^T + b1) W2^T + b2)
    mlp_fused<<<dim3(R_ / 128), blk, MLP_SMEM>>>(h, W1, b1, W2, b2, m2);

    // 3) mt[b][h][n] = m2[b][n][h]
    transpose_m<<<dim3(N_ / 32, H_ / 32, B_), dim3(32, 8)>>>(m2, mt);

    // 4) msg = relu(A_b @ m_b)  per batch: M=2048, N=128, K=2048 (NT vs mt)
    gemm_nt_split<1><<<dim3(1, N_ / BM, B_), blk>>>(
        A,  (long long)N_ * N_, N_,
        mt, (long long)H_ * N_, N_,
        nullptr,
        msg, (long long)N_ * H_, H_, N_);

    // 5) gx = msg @ W_ih^T + b_ih   [16384 x 384]
    gemm_nt_split<0><<<dim3(3 * H_ / BN, R_ / BM, 1), blk>>>(
        msg, 0, H_, Wih, 0, H_, bih, gx, 0, 3 * H_, H_);

    // 6) gh = h @ W_hh^T + b_hh
    gemm_nt_split<0><<<dim3(3 * H_ / BN, R_ / BM, 1), blk>>>(
        h, 0, H_, Whh, 0, H_, bhh, gh, 0, 3 * H_, H_);

    // 7) gates + output
    gru_gates<<<(R_ * H_ / 4 + 255) / 256, 256>>>(gx, gh, h, out);
}

// round 12
// speedup vs baseline: 1.4824x; 1.4824x over previous
#include <cuda_runtime.h>
#include <cuda_bf16.h>
#include <stdint.h>

// Problem dims (fixed by the reference)
#define B_  8
#define N_  2048
#define H_  128
#define R_  (B_ * N_)   // 16384 total rows

// GEMM tiling
#define BM 128
#define BN 128
#define BK 32
#define KP 40           // padded K stride (bf16) for BK=32 tiles
#define KP2 136         // padded K stride (bf16) for K=128 resident tiles
#define NTHREADS 256

// -------- scratch (__device__ globals: no allocation allowed) --------
__device__ float g_mt [B_ * H_ * N_];   // 8 MB   (m2 transposed per batch: [b][h][n])
__device__ float g_msg[R_ * H_];        // 8 MB

__device__ __forceinline__ uint32_t lds_u32(const __nv_bfloat16* p) {
    return *reinterpret_cast<const uint32_t*>(p);
}

__device__ __forceinline__ float sigm(float x) { return 1.f / (1.f + expf(-x)); }

__device__ __forceinline__ void mma_bf16(float* c,
                                         uint32_t a0, uint32_t a1, uint32_t a2, uint32_t a3,
                                         uint32_t b0, uint32_t b1) {
    asm volatile(
        "mma.sync.aligned.m16n8k16.row.col.f32.bf16.bf16.f32 "
        "{%0,%1,%2,%3}, {%4,%5,%6,%7}, {%8,%9}, {%0,%1,%2,%3};\n"
        : "+f"(c[0]), "+f"(c[1]), "+f"(c[2]), "+f"(c[3])
        : "r"(a0), "r"(a1), "r"(a2), "r"(a3), "r"(b0), "r"(b1));
}

// split a float4 into hi/lo bf16 and store as two bf162 pairs at smem offset `off`
__device__ __forceinline__ void split_store(__nv_bfloat16* shi, __nv_bfloat16* slo,
                                            int off, float4 v) {
    float va[4] = {v.x, v.y, v.z, v.w};
    __nv_bfloat16 hi[4], lo[4];
    #pragma unroll
    for (int q = 0; q < 4; q++) {
        hi[q] = __float2bfloat16(va[q]);
        lo[q] = __float2bfloat16(va[q] - __bfloat162float(hi[q]));
    }
    *reinterpret_cast<__nv_bfloat162*>(shi + off)     = __halves2bfloat162(hi[0], hi[1]);
    *reinterpret_cast<__nv_bfloat162*>(shi + off + 2) = __halves2bfloat162(hi[2], hi[3]);
    *reinterpret_cast<__nv_bfloat162*>(slo + off)     = __halves2bfloat162(lo[0], lo[1]);
    *reinterpret_cast<__nv_bfloat162*>(slo + off + 2) = __halves2bfloat162(lo[2], lo[3]);
}

// warp-tile MMA sweep over KC columns of hi/lo split tiles.
// A tile rows wrow..wrow+MI*16-1, B tile rows wcol..wcol+31, stride = padded K (bf16).
// 2-term split: hi*hi + hi*lo + lo*hi (fp32 accumulate) == fp32-grade product.
template<int STRIDE, int KC, int MI>
__device__ __forceinline__ void tile_mma(const __nv_bfloat16* sAhi, const __nv_bfloat16* sAlo,
                                         const __nv_bfloat16* sBhi, const __nv_bfloat16* sBlo,
                                         int wrow, int wcol, int lane,
                                         float acc[][4][4]) {
    const int arow = lane >> 2;        // 0..7
    const int kq   = (lane & 3) * 2;   // 0,2,4,6
    #pragma unroll
    for (int kk = 0; kk < KC; kk += 16) {
        uint32_t ah[MI][4], al[MI][4];
        #pragma unroll
        for (int i = 0; i < MI; i++) {
            const int base = (wrow + i * 16 + arow) * STRIDE + kk + kq;
            ah[i][0] = lds_u32(sAhi + base);
            ah[i][1] = lds_u32(sAhi + base + 8 * STRIDE);
            ah[i][2] = lds_u32(sAhi + base + 8);
            ah[i][3] = lds_u32(sAhi + base + 8 * STRIDE + 8);
            al[i][0] = lds_u32(sAlo + base);
            al[i][1] = lds_u32(sAlo + base + 8 * STRIDE);
            al[i][2] = lds_u32(sAlo + base + 8);
            al[i][3] = lds_u32(sAlo + base + 8 * STRIDE + 8);
        }
        uint32_t bh[4][2], bl[4][2];
        #pragma unroll
        for (int j = 0; j < 4; j++) {
            const int base = (wcol + j * 8 + arow) * STRIDE + kk + kq;
            bh[j][0] = lds_u32(sBhi + base);
            bh[j][1] = lds_u32(sBhi + base + 8);
            bl[j][0] = lds_u32(sBlo + base);
            bl[j][1] = lds_u32(sBlo + base + 8);
        }
        #pragma unroll
        for (int i = 0; i < MI; i++)
            #pragma unroll
            for (int j = 0; j < 4; j++) {
                mma_bf16(acc[i][j], ah[i][0], ah[i][1], ah[i][2], ah[i][3], bh[j][0], bh[j][1]);
                mma_bf16(acc[i][j], ah[i][0], ah[i][1], ah[i][2], ah[i][3], bl[j][0], bl[j][1]);
                mma_bf16(acc[i][j], al[i][0], al[i][1], al[i][2], al[i][3], bh[j][0], bh[j][1]);
            }
    }
}

// ---------------- adjacency GEMM: C = relu(A * B^T) ----------------
// Double-buffered smem (one __syncthreads per K-iter); register prefetch of next
// k-tile overlaps the MMA sweep; split-store after the sweep overlaps across warps.
// Dyn smem: 2 buffers x 4 arrays x BM*KP bf16 = 81,920 B.
template<int ACT>
__global__ void __launch_bounds__(NTHREADS, 1)
gemm_nt_split(const float* __restrict__ A, long long strideA, int lda,
              const float* __restrict__ Bm, long long strideB, int ldb,
              float* __restrict__ C, long long strideC, int ldc,
              int K)
{
    extern __shared__ __nv_bfloat16 s_g[];

    const int tid  = threadIdx.x;
    const int lane = tid & 31;
    const int warp = tid >> 5;
    const int wrow = (warp >> 2) * 64;
    const int wcol = (warp & 3) * 32;

    const long long bz = blockIdx.z;
    const float* Ag = A  + bz * strideA + (long long)blockIdx.y * BM * lda;
    const float* Bg = Bm + bz * strideB + (long long)blockIdx.x * BN * ldb;

    const int lr = tid >> 3;         // row 0..31 (+32p)
    const int lc = (tid & 7) * 4;    // float col 0..28

    float acc[4][4][4];
    #pragma unroll
    for (int i = 0; i < 4; i++)
        #pragma unroll
        for (int j = 0; j < 4; j++)
            #pragma unroll
            for (int t = 0; t < 4; t++) acc[i][j][t] = 0.f;

    // prologue: first k-tile -> buf0
    float4 ra[4], rb[4];
    #pragma unroll
    for (int p = 0; p < 4; p++) {
        ra[p] = *reinterpret_cast<const float4*>(Ag + (long long)(lr + 32 * p) * lda + lc);
        rb[p] = *reinterpret_cast<const float4*>(Bg + (long long)(lr + 32 * p) * ldb + lc);
    }
    {
        __nv_bfloat16* b0 = s_g;
        #pragma unroll
        for (int p = 0; p < 4; p++) {
            const int off = (lr + 32 * p) * KP + lc;
            split_store(b0,              b0 + BM * KP,     off, ra[p]);
            split_store(b0 + 2 * BM * KP, b0 + 3 * BM * KP, off, rb[p]);
        }
    }
    __syncthreads();

    const int nIt = K / BK;
    for (int it = 0; it < nIt; ++it) {
        const bool more = (it + 1) < nIt;
        if (more) {
            const int kn = (it + 1) * BK;
            #pragma unroll
            for (int p = 0; p < 4; p++) {
                ra[p] = *reinterpret_cast<const float4*>(Ag + (long long)(lr + 32 * p) * lda + (kn + lc));
                rb[p] = *reinterpret_cast<const float4*>(Bg + (long long)(lr + 32 * p) * ldb + (kn + lc));
            }
        }
        __nv_bfloat16* cb = s_g + (it & 1) * 4 * BM * KP;
        tile_mma<KP, BK, 4>(cb, cb + BM * KP, cb + 2 * BM * KP, cb + 3 * BM * KP,
                            wrow, wcol, lane, acc);
        if (more) {
            __nv_bfloat16* nb = s_g + ((it + 1) & 1) * 4 * BM * KP;
            #pragma unroll
            for (int p = 0; p < 4; p++) {
                const int off = (lr + 32 * p) * KP + lc;
                split_store(nb,              nb + BM * KP,     off, ra[p]);
                split_store(nb + 2 * BM * KP, nb + 3 * BM * KP, off, rb[p]);
            }
            __syncthreads();
        }
    }

    // epilogue: optional relu, fp32 store
    float* Cg = C + bz * strideC;
    const int rb0 = blockIdx.y * BM + wrow;
    const int cb0 = blockIdx.x * BN + wcol;
    #pragma unroll
    for (int i = 0; i < 4; i++) {
        const int r0 = rb0 + i * 16 + (lane >> 2);
        #pragma unroll
        for (int j = 0; j < 4; j++) {
            const int c0 = cb0 + j * 8 + (lane & 3) * 2;
            float v0 = acc[i][j][0], v1 = acc[i][j][1], v2 = acc[i][j][2], v3 = acc[i][j][3];
            if (ACT) {
                v0 = fmaxf(v0, 0.f); v1 = fmaxf(v1, 0.f);
                v2 = fmaxf(v2, 0.f); v3 = fmaxf(v3, 0.f);
            }
            *reinterpret_cast<float2*>(Cg + (long long)r0 * ldc + c0)       = make_float2(v0, v1);
            *reinterpret_cast<float2*>(Cg + (long long)(r0 + 8) * ldc + c0) = make_float2(v2, v3);
        }
    }
}

// -------- fused MLP: mt = transpose(relu(relu(h W1^T + b1) W2^T + b2)) --------
// One CTA per 128 rows. K=128 lives entirely in smem; m1 never touches HBM;
// output staged in smem and written TRANSPOSED directly (kills transpose kernel).
// Dyn smem: 4 arrays of [128][KP2] bf16 = 139,264 B.
__global__ void __launch_bounds__(NTHREADS, 1)
mlp_fused(const float* __restrict__ h,
          const float* __restrict__ W1, const float* __restrict__ b1,
          const float* __restrict__ W2, const float* __restrict__ b2,
          float* __restrict__ mt)
{
    extern __shared__ __nv_bfloat16 s_m[];
    __nv_bfloat16* sXhi = s_m;
    __nv_bfloat16* sXlo = sXhi + 128 * KP2;
    __nv_bfloat16* sWhi = sXlo + 128 * KP2;
    __nv_bfloat16* sWlo = sWhi + 128 * KP2;

    const int tid  = threadIdx.x;
    const int lane = tid & 31;
    const int warp = tid >> 5;
    const int wrow = (warp >> 2) * 64;
    const int wcol = (warp & 3) * 32;

    const float* Xg = h + (long long)blockIdx.x * 128 * H_;

    #pragma unroll
    for (int it = 0; it < 16; it++) {
        const int i   = tid + it * NTHREADS;      // 0..4095
        const int row = i >> 5;
        const int c4  = (i & 31) * 4;
        const int off = row * KP2 + c4;
        split_store(sXhi, sXlo, off, *reinterpret_cast<const float4*>(Xg + row * H_ + c4));
        split_store(sWhi, sWlo, off, *reinterpret_cast<const float4*>(W1 + row * H_ + c4));
    }
    __syncthreads();

    float acc[4][4][4];
    #pragma unroll
    for (int i = 0; i < 4; i++)
        #pragma unroll
        for (int j = 0; j < 4; j++)
            #pragma unroll
            for (int t = 0; t < 4; t++) acc[i][j][t] = 0.f;

    // ---- gemm1: X @ W1^T ----
    tile_mma<KP2, 128, 4>(sXhi, sXlo, sWhi, sWlo, wrow, wcol, lane, acc);
    __syncthreads();

    // relu(acc + b1) -> split back into sX (becomes m1 tile)
    #pragma unroll
    for (int i = 0; i < 4; i++) {
        const int row = wrow + i * 16 + (lane >> 2);
        #pragma unroll
        for (int j = 0; j < 4; j++) {
            const int col = wcol + j * 8 + (lane & 3) * 2;
            const float bb0 = b1[col], bb1 = b1[col + 1];
            float v0 = fmaxf(acc[i][j][0] + bb0, 0.f);
            float v1 = fmaxf(acc[i][j][1] + bb1, 0.f);
            float v2 = fmaxf(acc[i][j][2] + bb0, 0.f);
            float v3 = fmaxf(acc[i][j][3] + bb1, 0.f);
            __nv_bfloat16 h0 = __float2bfloat16(v0), h1 = __float2bfloat16(v1);
            __nv_bfloat16 h2 = __float2bfloat16(v2), h3 = __float2bfloat16(v3);
            __nv_bfloat16 l0 = __float2bfloat16(v0 - __bfloat162float(h0));
            __nv_bfloat16 l1 = __float2bfloat16(v1 - __bfloat162float(h1));
            __nv_bfloat16 l2 = __float2bfloat16(v2 - __bfloat162float(h2));
            __nv_bfloat16 l3 = __float2bfloat16(v3 - __bfloat162float(h3));
            *reinterpret_cast<__nv_bfloat162*>(sXhi + row * KP2 + col)       = __halves2bfloat162(h0, h1);
            *reinterpret_cast<__nv_bfloat162*>(sXlo + row * KP2 + col)       = __halves2bfloat162(l0, l1);
            *reinterpret_cast<__nv_bfloat162*>(sXhi + (row + 8) * KP2 + col) = __halves2bfloat162(h2, h3);
            *reinterpret_cast<__nv_bfloat162*>(sXlo + (row + 8) * KP2 + col) = __halves2bfloat162(l2, l3);
            acc[i][j][0] = acc[i][j][1] = acc[i][j][2] = acc[i][j][3] = 0.f;
        }
    }

    // load + split W2 (overwrites W1 tile)
    #pragma unroll
    for (int it = 0; it < 16; it++) {
        const int i   = tid + it * NTHREADS;
        const int row = i >> 5;
        const int c4  = (i & 31) * 4;
        split_store(sWhi, sWlo, row * KP2 + c4, *reinterpret_cast<const float4*>(W2 + row * H_ + c4));
    }
    __syncthreads();

    // ---- gemm2: m1 @ W2^T ----
    tile_mma<KP2, 128, 4>(sXhi, sXlo, sWhi, sWlo, wrow, wcol, lane, acc);
    __syncthreads();   // all warps done reading sW -> reuse as fp32 staging

    // stage relu(acc + b2) into smem [n_local][h], pad 129
    float* sOut = reinterpret_cast<float*>(sWhi);   // 128*129*4 = 66,048 B fits
    #pragma unroll
    for (int i = 0; i < 4; i++) {
        const int row = wrow + i * 16 + (lane >> 2);
        #pragma unroll
        for (int j = 0; j < 4; j++) {
            const int col = wcol + j * 8 + (lane & 3) * 2;
            const float bb0 = b2[col], bb1 = b2[col + 1];
            sOut[row * 129 + col]           = fmaxf(acc[i][j][0] + bb0, 0.f);
            sOut[row * 129 + col + 1]       = fmaxf(acc[i][j][1] + bb1, 0.f);
            sOut[(row + 8) * 129 + col]     = fmaxf(acc[i][j][2] + bb0, 0.f);
            sOut[(row + 8) * 129 + col + 1] = fmaxf(acc[i][j][3] + bb1, 0.f);
        }
    }
    __syncthreads();

    // transposed write-out: mt[b][h][n0+n]  (coalesced float4 along n)
    const int b  = blockIdx.x >> 4;           // 16 blocks per batch
    const int n0 = (blockIdx.x & 15) * 128;
    float* dst = mt + (long long)b * H_ * N_ + n0;
    #pragma unroll
    for (int it = 0; it < 16; it++) {
        const int i    = tid + it * NTHREADS;
        const int hrow = i >> 5;
        const int nc4  = (i & 31) * 4;
        float4 v = make_float4(sOut[(nc4 + 0) * 129 + hrow],
                               sOut[(nc4 + 1) * 129 + hrow],
                               sOut[(nc4 + 2) * 129 + hrow],
                               sOut[(nc4 + 3) * 129 + hrow]);
        *reinterpret_cast<float4*>(dst + (long long)hrow * N_ + nc4) = v;
    }
}

// -------- fused GRU: out = GRU(msg, h) with both gate GEMMs + gates in one kernel --
// CTA = 64 rows. msg & h tiles (K=128) resident in smem; per gate, Wih_g and Whh_g
// sweeps accumulate into ONE fragment (gx_g + gh_g) except the n-gate (needs r*gh_n).
// gx/gh never touch HBM. Dyn smem: 4x[64*KP2] + 2x[128*KP2] bf16 = 139,264 B.
__global__ void __launch_bounds__(NTHREADS, 1)
gru_fused(const float* __restrict__ msg, const float* __restrict__ h,
          const float* __restrict__ Wih, const float* __restrict__ Whh,
          const float* __restrict__ bih, const float* __restrict__ bhh,
          float* __restrict__ out)
{
    extern __shared__ __nv_bfloat16 s_r[];
    __nv_bfloat16* sMhi = s_r;                       // msg tile 64 x KP2
    __nv_bfloat16* sMlo = sMhi + 64 * KP2;
    __nv_bfloat16* sHhi = sMlo + 64 * KP2;           // h tile
    __nv_bfloat16* sHlo = sHhi + 64 * KP2;
    __nv_bfloat16* sWhi = sHlo + 64 * KP2;           // W gate slice 128 x KP2
    __nv_bfloat16* sWlo = sWhi + 128 * KP2;

    const int tid  = threadIdx.x;
    const int lane = tid & 31;
    const int warp = tid >> 5;
    const int wr   = (warp >> 2) * 32;   // warp row 0/32
    const int wc   = (warp & 3) * 32;    // warp col 0/32/64/96 (within 128-col gate)

    const long long row0 = (long long)blockIdx.x * 64;

    // load + split msg and h tiles: 64x128 fp32 each -> 2048 float4 each, 8/thread
    #pragma unroll
    for (int it = 0; it < 8; it++) {
        const int i   = tid + it * NTHREADS;   // 0..2047
        const int row = i >> 5;
        const int c4  = (i & 31) * 4;
        const int off = row * KP2 + c4;
        split_store(sMhi, sMlo, off, *reinterpret_cast<const float4*>(msg + (row0 + row) * H_ + c4));
        split_store(sHhi, sHlo, off, *reinterpret_cast<const float4*>(h   + (row0 + row) * H_ + c4));
    }

    // W slice loader: 128x128 fp32 -> smem split (sync before overwrite, sync after)
    auto loadW = [&](const float* __restrict__ Wslice) {
        __syncthreads();
        #pragma unroll
        for (int it = 0; it < 16; it++) {
            const int i   = tid + it * NTHREADS;
            const int row = i >> 5;
            const int c4  = (i & 31) * 4;
            split_store(sWhi, sWlo, row * KP2 + c4,
                        *reinterpret_cast<const float4*>(Wslice + row * H_ + c4));
        }
        __syncthreads();
    };

    float acc[2][4][4], rg[2][4][4], zg[2][4][4];
    #pragma unroll
    for (int i = 0; i < 2; i++)
        #pragma unroll
        for (int j = 0; j < 4; j++)
            #pragma unroll
            for (int t = 0; t < 4; t++) acc[i][j][t] = 0.f;

    // ---- r gate: acc = msg@Wih_r^T + h@Whh_r^T ----
    loadW(Wih);
    tile_mma<KP2, 128, 2>(sMhi, sMlo, sWhi, sWlo, wr, wc, lane, acc);
    loadW(Whh);
    tile_mma<KP2, 128, 2>(sHhi, sHlo, sWhi, sWlo, wr, wc, lane, acc);
    #pragma unroll
    for (int i = 0; i < 2; i++)
        #pragma unroll
        for (int j = 0; j < 4; j++) {
            const int c = wc + j * 8 + (lane & 3) * 2;
            const float bb0 = bih[c] + bhh[c], bb1 = bih[c + 1] + bhh[c + 1];
            rg[i][j][0] = sigm(acc[i][j][0] + bb0);
            rg[i][j][1] = sigm(acc[i][j][1] + bb1);
            rg[i][j][2] = sigm(acc[i][j][2] + bb0);
            rg[i][j][3] = sigm(acc[i][j][3] + bb1);
            acc[i][j][0] = acc[i][j][1] = acc[i][j][2] = acc[i][j][3] = 0.f;
        }

    // ---- z gate ----
    loadW(Wih + 128 * H_);
    tile_mma<KP2, 128, 2>(sMhi, sMlo, sWhi, sWlo, wr, wc, lane, acc);
    loadW(Whh + 128 * H_);
    tile_mma<KP2, 128, 2>(sHhi, sHlo, sWhi, sWlo, wr, wc, lane, acc);
    #pragma unroll
    for (int i = 0; i < 2; i++)
        #pragma unroll
        for (int j = 0; j < 4; j++) {
            const int c = wc + j * 8 + (lane & 3) * 2;
            const float bb0 = bih[128 + c] + bhh[128 + c], bb1 = bih[128 + c + 1] + bhh[128 + c + 1];
            zg[i][j][0] = sigm(acc[i][j][0] + bb0);
            zg[i][j][1] = sigm(acc[i][j][1] + bb1);
            zg[i][j][2] = sigm(acc[i][j][2] + bb0);
            zg[i][j][3] = sigm(acc[i][j][3] + bb1);
            acc[i][j][0] = acc[i][j][1] = acc[i][j][2] = acc[i][j][3] = 0.f;
        }

    // ---- n gate, h-side: rg <- rg * (h@Whh_n^T + bhh_n) ----
    loadW(Whh + 256 * H_);
    tile_mma<KP2, 128, 2>(sHhi, sHlo, sWhi, sWlo, wr, wc, lane, acc);
    #pragma unroll
    for (int i = 0; i < 2; i++)
        #pragma unroll
        for (int j = 0; j < 4; j++) {
            const int c = wc + j * 8 + (lane & 3) * 2;
            const float bb0 = bhh[256 + c], bb1 = bhh[256 + c + 1];
            rg[i][j][0] *= (acc[i][j][0] + bb0);
            rg[i][j][1] *= (acc[i][j][1] + bb1);
            rg[i][j][2] *= (acc[i][j][2] + bb0);
            rg[i][j][3] *= (acc[i][j][3] + bb1);
            acc[i][j][0] = acc[i][j][1] = acc[i][j][2] = acc[i][j][3] = 0.f;
        }

    // ---- n gate, x-side + combine ----
    loadW(Wih + 256 * H_);
    tile_mma<KP2, 128, 2>(sMhi, sMlo, sWhi, sWlo, wr, wc, lane, acc);

    #pragma unroll
    for (int i = 0; i < 2; i++) {
        const int rl = wr + i * 16 + (lane >> 2);
        #pragma unroll
        for (int j = 0; j < 4; j++) {
            const int c = wc + j * 8 + (lane & 3) * 2;
            const float bb0 = bih[256 + c], bb1 = bih[256 + c + 1];
            const float n0 = tanhf(acc[i][j][0] + bb0 + rg[i][j][0]);
            const float n1 = tanhf(acc[i][j][1] + bb1 + rg[i][j][1]);
            const float n2 = tanhf(acc[i][j][2] + bb0 + rg[i][j][2]);
            const float n3 = tanhf(acc[i][j][3] + bb1 + rg[i][j][3]);
            // reconstruct fp32 h from hi+lo split (err ~1e-5 rel)
            const float h0 = __bfloat162float(sHhi[rl * KP2 + c])       + __bfloat162float(sHlo[rl * KP2 + c]);
            const float h1 = __bfloat162float(sHhi[rl * KP2 + c + 1])   + __bfloat162float(sHlo[rl * KP2 + c + 1]);
            const float h2 = __bfloat162float(sHhi[(rl + 8) * KP2 + c])     + __bfloat162float(sHlo[(rl + 8) * KP2 + c]);
            const float h3 = __bfloat162float(sHhi[(rl + 8) * KP2 + c + 1]) + __bfloat162float(sHlo[(rl + 8) * KP2 + c + 1]);
            const float o0 = (1.f - zg[i][j][0]) * n0 + zg[i][j][0] * h0;
            const float o1 = (1.f - zg[i][j][1]) * n1 + zg[i][j][1] * h1;
            const float o2 = (1.f - zg[i][j][2]) * n2 + zg[i][j][2] * h2;
            const float o3 = (1.f - zg[i][j][3]) * n3 + zg[i][j][3] * h3;
            *reinterpret_cast<float2*>(out + (row0 + rl) * H_ + c)     = make_float2(o0, o1);
            *reinterpret_cast<float2*>(out + (row0 + rl + 8) * H_ + c) = make_float2(o2, o3);
        }
    }
}

extern "C" void kernel_launch(void* const* d_in, const int* in_sizes, int n_in,
                              void* d_out, int out_size)
{
    const float* h   = (const float*)d_in[0];   // [8,2048,128]
    const float* A   = (const float*)d_in[1];   // [8,2048,2048]
    const float* W1  = (const float*)d_in[2];   // [128,128]
    const float* b1  = (const float*)d_in[3];   // [128]
    const float* W2  = (const float*)d_in[4];   // [128,128]
    const float* b2  = (const float*)d_in[5];   // [128]
    const float* Wih = (const float*)d_in[6];   // [384,128]
    const float* Whh = (const float*)d_in[7];   // [384,128]
    const float* bih = (const float*)d_in[8];   // [384]
    const float* bhh = (const float*)d_in[9];   // [384]
    float* out = (float*)d_out;                 // [8,2048,128]

    float *mt, *msg;
    cudaGetSymbolAddress((void**)&mt,  g_mt);
    cudaGetSymbolAddress((void**)&msg, g_msg);

    const dim3 blk(NTHREADS);
    const int SMEM_MLP  = 4 * 128 * KP2 * (int)sizeof(__nv_bfloat16);            // 139264
    const int SMEM_GRU  = (4 * 64 + 2 * 128) * KP2 * (int)sizeof(__nv_bfloat16); // 139264
    const int SMEM_GEMM = 2 * 4 * BM * KP * (int)sizeof(__nv_bfloat16);          // 81920

    cudaFuncSetAttribute(mlp_fused,        cudaFuncAttributeMaxDynamicSharedMemorySize, SMEM_MLP);
    cudaFuncSetAttribute(gru_fused,        cudaFuncAttributeMaxDynamicSharedMemorySize, SMEM_GRU);
    cudaFuncSetAttribute(gemm_nt_split<1>, cudaFuncAttributeMaxDynamicSharedMemorySize, SMEM_GEMM);

    // 1) fused MLP + transpose: mt[b][h][n] = relu(relu(h W1^T+b1) W2^T+b2)^T
    mlp_fused<<<dim3(R_ / 128), blk, SMEM_MLP>>>(h, W1, b1, W2, b2, mt);

    // 2) msg = relu(A_b @ m_b)  per batch: M=2048, N=128, K=2048 (NT vs mt)
    gemm_nt_split<1><<<dim3(1, N_ / BM, B_), blk, SMEM_GEMM>>>(
        A,  (long long)N_ * N_, N_,
        mt, (long long)H_ * N_, N_,
        msg, (long long)N_ * H_, H_, N_);

    // 3) fused GRU: gate GEMMs + gate math + output combine
    gru_fused<<<dim3(R_ / 64), blk, SMEM_GRU>>>(msg, h, Wih, Whh, bih, bhh, out);
}

// round 13
// speedup vs baseline: 1.4934x; 1.0074x over previous
#include <cuda_runtime.h>
#include <cuda_bf16.h>
#include <stdint.h>

// Problem dims (fixed by the reference)
#define B_  8
#define N_  2048
#define H_  128
#define R_  (B_ * N_)   // 16384 total rows

// GEMM tiling
#define BM 128
#define BN 128
#define BK 32
#define KP 40           // padded K stride (bf16) for BK=32 tiles
#define KP2 136         // padded K stride (bf16) for K=128 resident tiles
#define NTHREADS 256

// -------- scratch (__device__ globals: no allocation allowed) --------
__device__ float g_mt [B_ * H_ * N_];   // 8 MB   (m2 transposed per batch: [b][h][n])
__device__ float g_msg[R_ * H_];        // 8 MB

__device__ __forceinline__ uint32_t lds_u32(const __nv_bfloat16* p) {
    return *reinterpret_cast<const uint32_t*>(p);
}

__device__ __forceinline__ float sigm(float x) { return 1.f / (1.f + expf(-x)); }

__device__ __forceinline__ void mma_bf16(float* c,
                                         uint32_t a0, uint32_t a1, uint32_t a2, uint32_t a3,
                                         uint32_t b0, uint32_t b1) {
    asm volatile(
        "mma.sync.aligned.m16n8k16.row.col.f32.bf16.bf16.f32 "
        "{%0,%1,%2,%3}, {%4,%5,%6,%7}, {%8,%9}, {%0,%1,%2,%3};\n"
        : "+f"(c[0]), "+f"(c[1]), "+f"(c[2]), "+f"(c[3])
        : "r"(a0), "r"(a1), "r"(a2), "r"(a3), "r"(b0), "r"(b1));
}

// split a float4 into hi/lo bf16 and store as two bf162 pairs at smem offset `off`
__device__ __forceinline__ void split_store(__nv_bfloat16* shi, __nv_bfloat16* slo,
                                            int off, float4 v) {
    float va[4] = {v.x, v.y, v.z, v.w};
    __nv_bfloat16 hi[4], lo[4];
    #pragma unroll
    for (int q = 0; q < 4; q++) {
        hi[q] = __float2bfloat16(va[q]);
        lo[q] = __float2bfloat16(va[q] - __bfloat162float(hi[q]));
    }
    *reinterpret_cast<__nv_bfloat162*>(shi + off)     = __halves2bfloat162(hi[0], hi[1]);
    *reinterpret_cast<__nv_bfloat162*>(shi + off + 2) = __halves2bfloat162(hi[2], hi[3]);
    *reinterpret_cast<__nv_bfloat162*>(slo + off)     = __halves2bfloat162(lo[0], lo[1]);
    *reinterpret_cast<__nv_bfloat162*>(slo + off + 2) = __halves2bfloat162(lo[2], lo[3]);
}

// warp-tile MMA sweep over KC columns of hi/lo split tiles.
// A tile rows wrow..wrow+MI*16-1, B tile rows wcol..wcol+31, stride = padded K (bf16).
// 2-term split: hi*hi + hi*lo + lo*hi (fp32 accumulate) == fp32-grade product.
template<int STRIDE, int KC, int MI>
__device__ __forceinline__ void tile_mma(const __nv_bfloat16* sAhi, const __nv_bfloat16* sAlo,
                                         const __nv_bfloat16* sBhi, const __nv_bfloat16* sBlo,
                                         int wrow, int wcol, int lane,
                                         float acc[][4][4]) {
    const int arow = lane >> 2;        // 0..7
    const int kq   = (lane & 3) * 2;   // 0,2,4,6
    #pragma unroll
    for (int kk = 0; kk < KC; kk += 16) {
        uint32_t ah[MI][4], al[MI][4];
        #pragma unroll
        for (int i = 0; i < MI; i++) {
            const int base = (wrow + i * 16 + arow) * STRIDE + kk + kq;
            ah[i][0] = lds_u32(sAhi + base);
            ah[i][1] = lds_u32(sAhi + base + 8 * STRIDE);
            ah[i][2] = lds_u32(sAhi + base + 8);
            ah[i][3] = lds_u32(sAhi + base + 8 * STRIDE + 8);
            al[i][0] = lds_u32(sAlo + base);
            al[i][1] = lds_u32(sAlo + base + 8 * STRIDE);
            al[i][2] = lds_u32(sAlo + base + 8);
            al[i][3] = lds_u32(sAlo + base + 8 * STRIDE + 8);
        }
        uint32_t bh[4][2], bl[4][2];
        #pragma unroll
        for (int j = 0; j < 4; j++) {
            const int base = (wcol + j * 8 + arow) * STRIDE + kk + kq;
            bh[j][0] = lds_u32(sBhi + base);
            bh[j][1] = lds_u32(sBhi + base + 8);
            bl[j][0] = lds_u32(sBlo + base);
            bl[j][1] = lds_u32(sBlo + base + 8);
        }
        #pragma unroll
        for (int i = 0; i < MI; i++)
            #pragma unroll
            for (int j = 0; j < 4; j++) {
                mma_bf16(acc[i][j], ah[i][0], ah[i][1], ah[i][2], ah[i][3], bh[j][0], bh[j][1]);
                mma_bf16(acc[i][j], ah[i][0], ah[i][1], ah[i][2], ah[i][3], bl[j][0], bl[j][1]);
                mma_bf16(acc[i][j], al[i][0], al[i][1], al[i][2], al[i][3], bh[j][0], bh[j][1]);
            }
    }
}

// ---------------- adjacency GEMM: C = relu(A * B^T) ----------------
// Double-buffered smem (one __syncthreads per K-iter); register prefetch of next
// k-tile overlaps the MMA sweep; split-store after the sweep overlaps across warps.
// Dyn smem: 2 buffers x 4 arrays x BM*KP bf16 = 81,920 B.
template<int ACT>
__global__ void __launch_bounds__(NTHREADS, 1)
gemm_nt_split(const float* __restrict__ A, long long strideA, int lda,
              const float* __restrict__ Bm, long long strideB, int ldb,
              float* __restrict__ C, long long strideC, int ldc,
              int K)
{
    extern __shared__ __nv_bfloat16 s_g[];

    const int tid  = threadIdx.x;
    const int lane = tid & 31;
    const int warp = tid >> 5;
    const int wrow = (warp >> 2) * 64;
    const int wcol = (warp & 3) * 32;

    const long long bz = blockIdx.z;
    const float* Ag = A  + bz * strideA + (long long)blockIdx.y * BM * lda;
    const float* Bg = Bm + bz * strideB + (long long)blockIdx.x * BN * ldb;

    const int lr = tid >> 3;         // row 0..31 (+32p)
    const int lc = (tid & 7) * 4;    // float col 0..28

    float acc[4][4][4];
    #pragma unroll
    for (int i = 0; i < 4; i++)
        #pragma unroll
        for (int j = 0; j < 4; j++)
            #pragma unroll
            for (int t = 0; t < 4; t++) acc[i][j][t] = 0.f;

    // prologue: first k-tile -> buf0
    float4 ra[4], rb[4];
    #pragma unroll
    for (int p = 0; p < 4; p++) {
        ra[p] = *reinterpret_cast<const float4*>(Ag + (long long)(lr + 32 * p) * lda + lc);
        rb[p] = *reinterpret_cast<const float4*>(Bg + (long long)(lr + 32 * p) * ldb + lc);
    }
    {
        __nv_bfloat16* b0 = s_g;
        #pragma unroll
        for (int p = 0; p < 4; p++) {
            const int off = (lr + 32 * p) * KP + lc;
            split_store(b0,              b0 + BM * KP,     off, ra[p]);
            split_store(b0 + 2 * BM * KP, b0 + 3 * BM * KP, off, rb[p]);
        }
    }
    __syncthreads();

    const int nIt = K / BK;
    for (int it = 0; it < nIt; ++it) {
        const bool more = (it + 1) < nIt;
        if (more) {
            const int kn = (it + 1) * BK;
            #pragma unroll
            for (int p = 0; p < 4; p++) {
                ra[p] = *reinterpret_cast<const float4*>(Ag + (long long)(lr + 32 * p) * lda + (kn + lc));
                rb[p] = *reinterpret_cast<const float4*>(Bg + (long long)(lr + 32 * p) * ldb + (kn + lc));
            }
        }
        __nv_bfloat16* cb = s_g + (it & 1) * 4 * BM * KP;
        tile_mma<KP, BK, 4>(cb, cb + BM * KP, cb + 2 * BM * KP, cb + 3 * BM * KP,
                            wrow, wcol, lane, acc);
        if (more) {
            __nv_bfloat16* nb = s_g + ((it + 1) & 1) * 4 * BM * KP;
            #pragma unroll
            for (int p = 0; p < 4; p++) {
                const int off = (lr + 32 * p) * KP + lc;
                split_store(nb,              nb + BM * KP,     off, ra[p]);
                split_store(nb + 2 * BM * KP, nb + 3 * BM * KP, off, rb[p]);
            }
            __syncthreads();
        }
    }

    // epilogue: optional relu, fp32 store
    float* Cg = C + bz * strideC;
    const int rb0 = blockIdx.y * BM + wrow;
    const int cb0 = blockIdx.x * BN + wcol;
    #pragma unroll
    for (int i = 0; i < 4; i++) {
        const int r0 = rb0 + i * 16 + (lane >> 2);
        #pragma unroll
        for (int j = 0; j < 4; j++) {
            const int c0 = cb0 + j * 8 + (lane & 3) * 2;
            float v0 = acc[i][j][0], v1 = acc[i][j][1], v2 = acc[i][j][2], v3 = acc[i][j][3];
            if (ACT) {
                v0 = fmaxf(v0, 0.f); v1 = fmaxf(v1, 0.f);
                v2 = fmaxf(v2, 0.f); v3 = fmaxf(v3, 0.f);
            }
            *reinterpret_cast<float2*>(Cg + (long long)r0 * ldc + c0)       = make_float2(v0, v1);
            *reinterpret_cast<float2*>(Cg + (long long)(r0 + 8) * ldc + c0) = make_float2(v2, v3);
        }
    }
}

// -------- fused MLP: mt = transpose(relu(relu(h W1^T + b1) W2^T + b2)) --------
// One CTA per 128 rows. K=128 lives entirely in smem; m1 never touches HBM;
// output staged in smem and written TRANSPOSED directly (kills transpose kernel).
// Dyn smem: 4 arrays of [128][KP2] bf16 = 139,264 B.
__global__ void __launch_bounds__(NTHREADS, 1)
mlp_fused(const float* __restrict__ h,
          const float* __restrict__ W1, const float* __restrict__ b1,
          const float* __restrict__ W2, const float* __restrict__ b2,
          float* __restrict__ mt)
{
    extern __shared__ __nv_bfloat16 s_m[];
    __nv_bfloat16* sXhi = s_m;
    __nv_bfloat16* sXlo = sXhi + 128 * KP2;
    __nv_bfloat16* sWhi = sXlo + 128 * KP2;
    __nv_bfloat16* sWlo = sWhi + 128 * KP2;

    const int tid  = threadIdx.x;
    const int lane = tid & 31;
    const int warp = tid >> 5;
    const int wrow = (warp >> 2) * 64;
    const int wcol = (warp & 3) * 32;

    const float* Xg = h + (long long)blockIdx.x * 128 * H_;

    #pragma unroll
    for (int it = 0; it < 16; it++) {
        const int i   = tid + it * NTHREADS;      // 0..4095
        const int row = i >> 5;
        const int c4  = (i & 31) * 4;
        const int off = row * KP2 + c4;
        split_store(sXhi, sXlo, off, *reinterpret_cast<const float4*>(Xg + row * H_ + c4));
        split_store(sWhi, sWlo, off, *reinterpret_cast<const float4*>(W1 + row * H_ + c4));
    }
    __syncthreads();

    float acc[4][4][4];
    #pragma unroll
    for (int i = 0; i < 4; i++)
        #pragma unroll
        for (int j = 0; j < 4; j++)
            #pragma unroll
            for (int t = 0; t < 4; t++) acc[i][j][t] = 0.f;

    // ---- gemm1: X @ W1^T ----
    tile_mma<KP2, 128, 4>(sXhi, sXlo, sWhi, sWlo, wrow, wcol, lane, acc);
    __syncthreads();

    // relu(acc + b1) -> split back into sX (becomes m1 tile)
    #pragma unroll
    for (int i = 0; i < 4; i++) {
        const int row = wrow + i * 16 + (lane >> 2);
        #pragma unroll
        for (int j = 0; j < 4; j++) {
            const int col = wcol + j * 8 + (lane & 3) * 2;
            const float bb0 = b1[col], bb1 = b1[col + 1];
            float v0 = fmaxf(acc[i][j][0] + bb0, 0.f);
            float v1 = fmaxf(acc[i][j][1] + bb1, 0.f);
            float v2 = fmaxf(acc[i][j][2] + bb0, 0.f);
            float v3 = fmaxf(acc[i][j][3] + bb1, 0.f);
            __nv_bfloat16 h0 = __float2bfloat16(v0), h1 = __float2bfloat16(v1);
            __nv_bfloat16 h2 = __float2bfloat16(v2), h3 = __float2bfloat16(v3);
            __nv_bfloat16 l0 = __float2bfloat16(v0 - __bfloat162float(h0));
            __nv_bfloat16 l1 = __float2bfloat16(v1 - __bfloat162float(h1));
            __nv_bfloat16 l2 = __float2bfloat16(v2 - __bfloat162float(h2));
            __nv_bfloat16 l3 = __float2bfloat16(v3 - __bfloat162float(h3));
            *reinterpret_cast<__nv_bfloat162*>(sXhi + row * KP2 + col)       = __halves2bfloat162(h0, h1);
            *reinterpret_cast<__nv_bfloat162*>(sXlo + row * KP2 + col)       = __halves2bfloat162(l0, l1);
            *reinterpret_cast<__nv_bfloat162*>(sXhi + (row + 8) * KP2 + col) = __halves2bfloat162(h2, h3);
            *reinterpret_cast<__nv_bfloat162*>(sXlo + (row + 8) * KP2 + col) = __halves2bfloat162(l2, l3);
            acc[i][j][0] = acc[i][j][1] = acc[i][j][2] = acc[i][j][3] = 0.f;
        }
    }

    // load + split W2 (overwrites W1 tile)
    #pragma unroll
    for (int it = 0; it < 16; it++) {
        const int i   = tid + it * NTHREADS;
        const int row = i >> 5;
        const int c4  = (i & 31) * 4;
        split_store(sWhi, sWlo, row * KP2 + c4, *reinterpret_cast<const float4*>(W2 + row * H_ + c4));
    }
    __syncthreads();

    // ---- gemm2: m1 @ W2^T ----
    tile_mma<KP2, 128, 4>(sXhi, sXlo, sWhi, sWlo, wrow, wcol, lane, acc);
    __syncthreads();   // all warps done reading sW -> reuse as fp32 staging

    // stage relu(acc + b2) into smem [n_local][h], pad 129
    float* sOut = reinterpret_cast<float*>(sWhi);   // 128*129*4 = 66,048 B fits
    #pragma unroll
    for (int i = 0; i < 4; i++) {
        const int row = wrow + i * 16 + (lane >> 2);
        #pragma unroll
        for (int j = 0; j < 4; j++) {
            const int col = wcol + j * 8 + (lane & 3) * 2;
            const float bb0 = b2[col], bb1 = b2[col + 1];
            sOut[row * 129 + col]           = fmaxf(acc[i][j][0] + bb0, 0.f);
            sOut[row * 129 + col + 1]       = fmaxf(acc[i][j][1] + bb1, 0.f);
            sOut[(row + 8) * 129 + col]     = fmaxf(acc[i][j][2] + bb0, 0.f);
            sOut[(row + 8) * 129 + col + 1] = fmaxf(acc[i][j][3] + bb1, 0.f);
        }
    }
    __syncthreads();

    // transposed write-out: mt[b][h][n0+n]  (coalesced float4 along n)
    const int b  = blockIdx.x >> 4;           // 16 blocks per batch
    const int n0 = (blockIdx.x & 15) * 128;
    float* dst = mt + (long long)b * H_ * N_ + n0;
    #pragma unroll
    for (int it = 0; it < 16; it++) {
        const int i    = tid + it * NTHREADS;
        const int hrow = i >> 5;
        const int nc4  = (i & 31) * 4;
        float4 v = make_float4(sOut[(nc4 + 0) * 129 + hrow],
                               sOut[(nc4 + 1) * 129 + hrow],
                               sOut[(nc4 + 2) * 129 + hrow],
                               sOut[(nc4 + 3) * 129 + hrow]);
        *reinterpret_cast<float4*>(dst + (long long)hrow * N_ + nc4) = v;
    }
}

// -------- fused GRU: out = GRU(msg, h) with both gate GEMMs + gates in one kernel --
// CTA = 64 rows. msg & h tiles (K=128) resident in smem; per gate, Wih_g and Whh_g
// sweeps accumulate into ONE fragment (gx_g + gh_g) except the n-gate (needs r*gh_n).
// gx/gh never touch HBM. Dyn smem: 4x[64*KP2] + 2x[128*KP2] bf16 = 139,264 B.
__global__ void __launch_bounds__(NTHREADS, 1)
gru_fused(const float* __restrict__ msg, const float* __restrict__ h,
          const float* __restrict__ Wih, const float* __restrict__ Whh,
          const float* __restrict__ bih, const float* __restrict__ bhh,
          float* __restrict__ out)
{
    extern __shared__ __nv_bfloat16 s_r[];
    __nv_bfloat16* sMhi = s_r;                       // msg tile 64 x KP2
    __nv_bfloat16* sMlo = sMhi + 64 * KP2;
    __nv_bfloat16* sHhi = sMlo + 64 * KP2;           // h tile
    __nv_bfloat16* sHlo = sHhi + 64 * KP2;
    __nv_bfloat16* sWhi = sHlo + 64 * KP2;           // W gate slice 128 x KP2
    __nv_bfloat16* sWlo = sWhi + 128 * KP2;

    const int tid  = threadIdx.x;
    const int lane = tid & 31;
    const int warp = tid >> 5;
    const int wr   = (warp >> 2) * 32;   // warp row 0/32
    const int wc   = (warp & 3) * 32;    // warp col 0/32/64/96 (within 128-col gate)

    const long long row0 = (long long)blockIdx.x * 64;

    // load + split msg and h tiles: 64x128 fp32 each -> 2048 float4 each, 8/thread
    #pragma unroll
    for (int it = 0; it < 8; it++) {
        const int i   = tid + it * NTHREADS;   // 0..2047
        const int row = i >> 5;
        const int c4  = (i & 31) * 4;
        const int off = row * KP2 + c4;
        split_store(sMhi, sMlo, off, *reinterpret_cast<const float4*>(msg + (row0 + row) * H_ + c4));
        split_store(sHhi, sHlo, off, *reinterpret_cast<const float4*>(h   + (row0 + row) * H_ + c4));
    }

    // W slice loader: 128x128 fp32 -> smem split (sync before overwrite, sync after)
    auto loadW = [&](const float* __restrict__ Wslice) {
        __syncthreads();
        #pragma unroll
        for (int it = 0; it < 16; it++) {
            const int i   = tid + it * NTHREADS;
            const int row = i >> 5;
            const int c4  = (i & 31) * 4;
            split_store(sWhi, sWlo, row * KP2 + c4,
                        *reinterpret_cast<const float4*>(Wslice + row * H_ + c4));
        }
        __syncthreads();
    };

    float acc[2][4][4], rg[2][4][4], zg[2][4][4];
    #pragma unroll
    for (int i = 0; i < 2; i++)
        #pragma unroll
        for (int j = 0; j < 4; j++)
            #pragma unroll
            for (int t = 0; t < 4; t++) acc[i][j][t] = 0.f;

    // ---- r gate: acc = msg@Wih_r^T + h@Whh_r^T ----
    loadW(Wih);
    tile_mma<KP2, 128, 2>(sMhi, sMlo, sWhi, sWlo, wr, wc, lane, acc);
    loadW(Whh);
    tile_mma<KP2, 128, 2>(sHhi, sHlo, sWhi, sWlo, wr, wc, lane, acc);
    #pragma unroll
    for (int i = 0; i < 2; i++)
        #pragma unroll
        for (int j = 0; j < 4; j++) {
            const int c = wc + j * 8 + (lane & 3) * 2;
            const float bb0 = bih[c] + bhh[c], bb1 = bih[c + 1] + bhh[c + 1];
            rg[i][j][0] = sigm(acc[i][j][0] + bb0);
            rg[i][j][1] = sigm(acc[i][j][1] + bb1);
            rg[i][j][2] = sigm(acc[i][j][2] + bb0);
            rg[i][j][3] = sigm(acc[i][j][3] + bb1);
            acc[i][j][0] = acc[i][j][1] = acc[i][j][2] = acc[i][j][3] = 0.f;
        }

    // ---- z gate ----
    loadW(Wih + 128 * H_);
    tile_mma<KP2, 128, 2>(sMhi, sMlo, sWhi, sWlo, wr, wc, lane, acc);
    loadW(Whh + 128 * H_);
    tile_mma<KP2, 128, 2>(sHhi, sHlo, sWhi, sWlo, wr, wc, lane, acc);
    #pragma unroll
    for (int i = 0; i < 2; i++)
        #pragma unroll
        for (int j = 0; j < 4; j++) {
            const int c = wc + j * 8 + (lane & 3) * 2;
            const float bb0 = bih[128 + c] + bhh[128 + c], bb1 = bih[128 + c + 1] + bhh[128 + c + 1];
            zg[i][j][0] = sigm(acc[i][j][0] + bb0);
            zg[i][j][1] = sigm(acc[i][j][1] + bb1);
            zg[i][j][2] = sigm(acc[i][j][2] + bb0);
            zg[i][j][3] = sigm(acc[i][j][3] + bb1);
            acc[i][j][0] = acc[i][j][1] = acc[i][j][2] = acc[i][j][3] = 0.f;
        }

    // ---- n gate, h-side: rg <- rg * (h@Whh_n^T + bhh_n) ----
    loadW(Whh + 256 * H_);
    tile_mma<KP2, 128, 2>(sHhi, sHlo, sWhi, sWlo, wr, wc, lane, acc);
    #pragma unroll
    for (int i = 0; i < 2; i++)
        #pragma unroll
        for (int j = 0; j < 4; j++) {
            const int c = wc + j * 8 + (lane & 3) * 2;
            const float bb0 = bhh[256 + c], bb1 = bhh[256 + c + 1];
            rg[i][j][0] *= (acc[i][j][0] + bb0);
            rg[i][j][1] *= (acc[i][j][1] + bb1);
            rg[i][j][2] *= (acc[i][j][2] + bb0);
            rg[i][j][3] *= (acc[i][j][3] + bb1);
            acc[i][j][0] = acc[i][j][1] = acc[i][j][2] = acc[i][j][3] = 0.f;
        }

    // ---- n gate, x-side + combine ----
    loadW(Wih + 256 * H_);
    tile_mma<KP2, 128, 2>(sMhi, sMlo, sWhi, sWlo, wr, wc, lane, acc);

    #pragma unroll
    for (int i = 0; i < 2; i++) {
        const int rl = wr + i * 16 + (lane >> 2);
        #pragma unroll
        for (int j = 0; j < 4; j++) {
            const int c = wc + j * 8 + (lane & 3) * 2;
            const float bb0 = bih[256 + c], bb1 = bih[256 + c + 1];
            const float n0 = tanhf(acc[i][j][0] + bb0 + rg[i][j][0]);
            const float n1 = tanhf(acc[i][j][1] + bb1 + rg[i][j][1]);
            const float n2 = tanhf(acc[i][j][2] + bb0 + rg[i][j][2]);
            const float n3 = tanhf(acc[i][j][3] + bb1 + rg[i][j][3]);
            // reconstruct fp32 h from hi+lo split (err ~1e-5 rel)
            const float h0 = __bfloat162float(sHhi[rl * KP2 + c])       + __bfloat162float(sHlo[rl * KP2 + c]);
            const float h1 = __bfloat162float(sHhi[rl * KP2 + c + 1])   + __bfloat162float(sHlo[rl * KP2 + c + 1]);
            const float h2 = __bfloat162float(sHhi[(rl + 8) * KP2 + c])     + __bfloat162float(sHlo[(rl + 8) * KP2 + c]);
            const float h3 = __bfloat162float(sHhi[(rl + 8) * KP2 + c + 1]) + __bfloat162float(sHlo[(rl + 8) * KP2 + c + 1]);
            const float o0 = (1.f - zg[i][j][0]) * n0 + zg[i][j][0] * h0;
            const float o1 = (1.f - zg[i][j][1]) * n1 + zg[i][j][1] * h1;
            const float o2 = (1.f - zg[i][j][2]) * n2 + zg[i][j][2] * h2;
            const float o3 = (1.f - zg[i][j][3]) * n3 + zg[i][j][3] * h3;
            *reinterpret_cast<float2*>(out + (row0 + rl) * H_ + c)     = make_float2(o0, o1);
            *reinterpret_cast<float2*>(out + (row0 + rl + 8) * H_ + c) = make_float2(o2, o3);
        }
    }
}

extern "C" void kernel_launch(void* const* d_in, const int* in_sizes, int n_in,
                              void* d_out, int out_size)
{
    const float* h   = (const float*)d_in[0];   // [8,2048,128]
    const float* A   = (const float*)d_in[1];   // [8,2048,2048]
    const float* W1  = (const float*)d_in[2];   // [128,128]
    const float* b1  = (const float*)d_in[3];   // [128]
    const float* W2  = (const float*)d_in[4];   // [128,128]
    const float* b2  = (const float*)d_in[5];   // [128]
    const float* Wih = (const float*)d_in[6];   // [384,128]
    const float* Whh = (const float*)d_in[7];   // [384,128]
    const float* bih = (const float*)d_in[8];   // [384]
    const float* bhh = (const float*)d_in[9];   // [384]
    float* out = (float*)d_out;                 // [8,2048,128]

    float *mt, *msg;
    cudaGetSymbolAddress((void**)&mt,  g_mt);
    cudaGetSymbolAddress((void**)&msg, g_msg);

    const dim3 blk(NTHREADS);
    const int SMEM_MLP  = 4 * 128 * KP2 * (int)sizeof(__nv_bfloat16);            // 139264
    const int SMEM_GRU  = (4 * 64 + 2 * 128) * KP2 * (int)sizeof(__nv_bfloat16); // 139264
    const int SMEM_GEMM = 2 * 4 * BM * KP * (int)sizeof(__nv_bfloat16);          // 81920

    cudaFuncSetAttribute(mlp_fused,        cudaFuncAttributeMaxDynamicSharedMemorySize, SMEM_MLP);
    cudaFuncSetAttribute(gru_fused,        cudaFuncAttributeMaxDynamicSharedMemorySize, SMEM_GRU);
    cudaFuncSetAttribute(gemm_nt_split<1>, cudaFuncAttributeMaxDynamicSharedMemorySize, SMEM_GEMM);

    // 1) fused MLP + transpose: mt[b][h][n] = relu(relu(h W1^T+b1) W2^T+b2)^T
    mlp_fused<<<dim3(R_ / 128), blk, SMEM_MLP>>>(h, W1, b1, W2, b2, mt);

    // 2) msg = relu(A_b @ m_b)  per batch: M=2048, N=128, K=2048 (NT vs mt)
    gemm_nt_split<1><<<dim3(1, N_ / BM, B_), blk, SMEM_GEMM>>>(
        A,  (long long)N_ * N_, N_,
        mt, (long long)H_ * N_, N_,
        msg, (long long)N_ * H_, H_, N_);

    // 3) fused GRU: gate GEMMs + gate math + output combine
    gru_fused<<<dim3(R_ / 64), blk, SMEM_GRU>>>(msg, h, Wih, Whh, bih, bhh, out);
}

// round 14
// speedup vs baseline: 1.6650x; 1.1149x over previous
#include <cuda_runtime.h>
#include <cuda_bf16.h>
#include <stdint.h>

// Problem dims (fixed by the reference)
#define B_  8
#define N_  2048
#define H_  128
#define R_  (B_ * N_)   // 16384 total rows

// GEMM tiling
#define BM 128
#define BN 128
#define BK 32
#define KP 40           // padded K stride (bf16) for BK=32 tiles
#define KP2 136         // padded K stride (bf16) for K=128 resident tiles
#define NT 512          // threads per CTA everywhere (16 warps, 4 per SMSP)

// -------- scratch (__device__ globals: no allocation allowed) --------
__device__ float g_mt [B_ * H_ * N_];   // 8 MB   (m2 transposed per batch: [b][h][n])
__device__ float g_msg[R_ * H_];        // 8 MB

__device__ __forceinline__ uint32_t lds_u32(const __nv_bfloat16* p) {
    return *reinterpret_cast<const uint32_t*>(p);
}

__device__ __forceinline__ float sigm(float x) { return 1.f / (1.f + expf(-x)); }

__device__ __forceinline__ void mma_bf16(float* c,
                                         uint32_t a0, uint32_t a1, uint32_t a2, uint32_t a3,
                                         uint32_t b0, uint32_t b1) {
    asm volatile(
        "mma.sync.aligned.m16n8k16.row.col.f32.bf16.bf16.f32 "
        "{%0,%1,%2,%3}, {%4,%5,%6,%7}, {%8,%9}, {%0,%1,%2,%3};\n"
        : "+f"(c[0]), "+f"(c[1]), "+f"(c[2]), "+f"(c[3])
        : "r"(a0), "r"(a1), "r"(a2), "r"(a3), "r"(b0), "r"(b1));
}

// split a float4 into hi/lo bf16 and store as two bf162 pairs at smem offset `off`
__device__ __forceinline__ void split_store(__nv_bfloat16* shi, __nv_bfloat16* slo,
                                            int off, float4 v) {
    float va[4] = {v.x, v.y, v.z, v.w};
    __nv_bfloat16 hi[4], lo[4];
    #pragma unroll
    for (int q = 0; q < 4; q++) {
        hi[q] = __float2bfloat16(va[q]);
        lo[q] = __float2bfloat16(va[q] - __bfloat162float(hi[q]));
    }
    *reinterpret_cast<__nv_bfloat162*>(shi + off)     = __halves2bfloat162(hi[0], hi[1]);
    *reinterpret_cast<__nv_bfloat162*>(shi + off + 2) = __halves2bfloat162(hi[2], hi[3]);
    *reinterpret_cast<__nv_bfloat162*>(slo + off)     = __halves2bfloat162(lo[0], lo[1]);
    *reinterpret_cast<__nv_bfloat162*>(slo + off + 2) = __halves2bfloat162(lo[2], lo[3]);
}

// warp-tile MMA sweep over KC columns of hi/lo split tiles.
// A tile rows wrow..wrow+MI*16-1, B tile rows wcol..wcol+31, stride = padded K (bf16).
// 2-term split: hi*hi + hi*lo + lo*hi (fp32 accumulate) == fp32-grade product.
template<int STRIDE, int KC, int MI>
__device__ __forceinline__ void tile_mma(const __nv_bfloat16* sAhi, const __nv_bfloat16* sAlo,
                                         const __nv_bfloat16* sBhi, const __nv_bfloat16* sBlo,
                                         int wrow, int wcol, int lane,
                                         float acc[][4][4]) {
    const int arow = lane >> 2;        // 0..7
    const int kq   = (lane & 3) * 2;   // 0,2,4,6
    #pragma unroll
    for (int kk = 0; kk < KC; kk += 16) {
        uint32_t ah[MI][4], al[MI][4];
        #pragma unroll
        for (int i = 0; i < MI; i++) {
            const int base = (wrow + i * 16 + arow) * STRIDE + kk + kq;
            ah[i][0] = lds_u32(sAhi + base);
            ah[i][1] = lds_u32(sAhi + base + 8 * STRIDE);
            ah[i][2] = lds_u32(sAhi + base + 8);
            ah[i][3] = lds_u32(sAhi + base + 8 * STRIDE + 8);
            al[i][0] = lds_u32(sAlo + base);
            al[i][1] = lds_u32(sAlo + base + 8 * STRIDE);
            al[i][2] = lds_u32(sAlo + base + 8);
            al[i][3] = lds_u32(sAlo + base + 8 * STRIDE + 8);
        }
        uint32_t bh[4][2], bl[4][2];
        #pragma unroll
        for (int j = 0; j < 4; j++) {
            const int base = (wcol + j * 8 + arow) * STRIDE + kk + kq;
            bh[j][0] = lds_u32(sBhi + base);
            bh[j][1] = lds_u32(sBhi + base + 8);
            bl[j][0] = lds_u32(sBlo + base);
            bl[j][1] = lds_u32(sBlo + base + 8);
        }
        #pragma unroll
        for (int i = 0; i < MI; i++)
            #pragma unroll
            for (int j = 0; j < 4; j++) {
                mma_bf16(acc[i][j], ah[i][0], ah[i][1], ah[i][2], ah[i][3], bh[j][0], bh[j][1]);
                mma_bf16(acc[i][j], ah[i][0], ah[i][1], ah[i][2], ah[i][3], bl[j][0], bl[j][1]);
                mma_bf16(acc[i][j], al[i][0], al[i][1], al[i][2], al[i][3], bh[j][0], bh[j][1]);
            }
    }
}

// ---------------- adjacency GEMM: C = relu(A * B^T) ----------------
// 512 threads, 16 warps (4x4), warp tile 32x32. Double-buffered smem; register
// prefetch of next k-tile overlaps the MMA sweep. Dyn smem 81,920 B.
__global__ void __launch_bounds__(NT, 1)
gemm_nt_relu(const float* __restrict__ A, long long strideA, int lda,
             const float* __restrict__ Bm, long long strideB, int ldb,
             float* __restrict__ C, long long strideC, int ldc,
             int K)
{
    extern __shared__ __nv_bfloat16 s_g[];

    const int tid  = threadIdx.x;
    const int lane = tid & 31;
    const int warp = tid >> 5;
    const int wrow = (warp >> 2) * 32;
    const int wcol = (warp & 3) * 32;

    const long long bz = blockIdx.z;
    const float* Ag = A  + bz * strideA + (long long)blockIdx.y * BM * lda;
    const float* Bg = Bm + bz * strideB + (long long)blockIdx.x * BN * ldb;

    const int lr = tid >> 3;         // row 0..63 (+64)
    const int lc = (tid & 7) * 4;    // float col 0..28

    float acc[2][4][4];
    #pragma unroll
    for (int i = 0; i < 2; i++)
        #pragma unroll
        for (int j = 0; j < 4; j++)
            #pragma unroll
            for (int t = 0; t < 4; t++) acc[i][j][t] = 0.f;

    // prologue: first k-tile -> buf0
    float4 ra[2], rb[2];
    #pragma unroll
    for (int p = 0; p < 2; p++) {
        ra[p] = *reinterpret_cast<const float4*>(Ag + (long long)(lr + 64 * p) * lda + lc);
        rb[p] = *reinterpret_cast<const float4*>(Bg + (long long)(lr + 64 * p) * ldb + lc);
    }
    {
        __nv_bfloat16* b0 = s_g;
        #pragma unroll
        for (int p = 0; p < 2; p++) {
            const int off = (lr + 64 * p) * KP + lc;
            split_store(b0,               b0 + BM * KP,     off, ra[p]);
            split_store(b0 + 2 * BM * KP, b0 + 3 * BM * KP, off, rb[p]);
        }
    }
    __syncthreads();

    const int nIt = K / BK;
    for (int it = 0; it < nIt; ++it) {
        const bool more = (it + 1) < nIt;
        if (more) {
            const int kn = (it + 1) * BK;
            #pragma unroll
            for (int p = 0; p < 2; p++) {
                ra[p] = *reinterpret_cast<const float4*>(Ag + (long long)(lr + 64 * p) * lda + (kn + lc));
                rb[p] = *reinterpret_cast<const float4*>(Bg + (long long)(lr + 64 * p) * ldb + (kn + lc));
            }
        }
        __nv_bfloat16* cb = s_g + (it & 1) * 4 * BM * KP;
        tile_mma<KP, BK, 2>(cb, cb + BM * KP, cb + 2 * BM * KP, cb + 3 * BM * KP,
                            wrow, wcol, lane, acc);
        if (more) {
            __nv_bfloat16* nb = s_g + ((it + 1) & 1) * 4 * BM * KP;
            #pragma unroll
            for (int p = 0; p < 2; p++) {
                const int off = (lr + 64 * p) * KP + lc;
                split_store(nb,               nb + BM * KP,     off, ra[p]);
                split_store(nb + 2 * BM * KP, nb + 3 * BM * KP, off, rb[p]);
            }
            __syncthreads();
        }
    }

    // epilogue: relu, fp32 store
    float* Cg = C + bz * strideC;
    const int rb0 = blockIdx.y * BM + wrow;
    const int cb0 = blockIdx.x * BN + wcol;
    #pragma unroll
    for (int i = 0; i < 2; i++) {
        const int r0 = rb0 + i * 16 + (lane >> 2);
        #pragma unroll
        for (int j = 0; j < 4; j++) {
            const int c0 = cb0 + j * 8 + (lane & 3) * 2;
            float v0 = fmaxf(acc[i][j][0], 0.f), v1 = fmaxf(acc[i][j][1], 0.f);
            float v2 = fmaxf(acc[i][j][2], 0.f), v3 = fmaxf(acc[i][j][3], 0.f);
            *reinterpret_cast<float2*>(Cg + (long long)r0 * ldc + c0)       = make_float2(v0, v1);
            *reinterpret_cast<float2*>(Cg + (long long)(r0 + 8) * ldc + c0) = make_float2(v2, v3);
        }
    }
}

// -------- fused MLP: mt = transpose(relu(relu(h W1^T + b1) W2^T + b2)) --------
// 512 threads, warp tile 32x32. One CTA per 128 rows; K=128 resident in smem;
// m1 never touches HBM; output staged in smem and written TRANSPOSED.
// Dyn smem: 4 arrays of [128][KP2] bf16 = 139,264 B.
__global__ void __launch_bounds__(NT, 1)
mlp_fused(const float* __restrict__ h,
          const float* __restrict__ W1, const float* __restrict__ b1,
          const float* __restrict__ W2, const float* __restrict__ b2,
          float* __restrict__ mt)
{
    extern __shared__ __nv_bfloat16 s_m[];
    __nv_bfloat16* sXhi = s_m;
    __nv_bfloat16* sXlo = sXhi + 128 * KP2;
    __nv_bfloat16* sWhi = sXlo + 128 * KP2;
    __nv_bfloat16* sWlo = sWhi + 128 * KP2;

    const int tid  = threadIdx.x;
    const int lane = tid & 31;
    const int warp = tid >> 5;
    const int wrow = (warp >> 2) * 32;
    const int wcol = (warp & 3) * 32;

    const float* Xg = h + (long long)blockIdx.x * 128 * H_;

    #pragma unroll
    for (int it = 0; it < 8; it++) {
        const int i   = tid + it * NT;           // 0..4095
        const int row = i >> 5;
        const int c4  = (i & 31) * 4;
        const int off = row * KP2 + c4;
        split_store(sXhi, sXlo, off, *reinterpret_cast<const float4*>(Xg + row * H_ + c4));
        split_store(sWhi, sWlo, off, *reinterpret_cast<const float4*>(W1 + row * H_ + c4));
    }
    __syncthreads();

    float acc[2][4][4];
    #pragma unroll
    for (int i = 0; i < 2; i++)
        #pragma unroll
        for (int j = 0; j < 4; j++)
            #pragma unroll
            for (int t = 0; t < 4; t++) acc[i][j][t] = 0.f;

    // ---- gemm1: X @ W1^T ----
    tile_mma<KP2, 128, 2>(sXhi, sXlo, sWhi, sWlo, wrow, wcol, lane, acc);
    __syncthreads();

    // relu(acc + b1) -> split back into sX (becomes m1 tile)
    #pragma unroll
    for (int i = 0; i < 2; i++) {
        const int row = wrow + i * 16 + (lane >> 2);
        #pragma unroll
        for (int j = 0; j < 4; j++) {
            const int col = wcol + j * 8 + (lane & 3) * 2;
            const float bb0 = b1[col], bb1 = b1[col + 1];
            float v0 = fmaxf(acc[i][j][0] + bb0, 0.f);
            float v1 = fmaxf(acc[i][j][1] + bb1, 0.f);
            float v2 = fmaxf(acc[i][j][2] + bb0, 0.f);
            float v3 = fmaxf(acc[i][j][3] + bb1, 0.f);
            __nv_bfloat16 h0 = __float2bfloat16(v0), h1 = __float2bfloat16(v1);
            __nv_bfloat16 h2 = __float2bfloat16(v2), h3 = __float2bfloat16(v3);
            __nv_bfloat16 l0 = __float2bfloat16(v0 - __bfloat162float(h0));
            __nv_bfloat16 l1 = __float2bfloat16(v1 - __bfloat162float(h1));
            __nv_bfloat16 l2 = __float2bfloat16(v2 - __bfloat162float(h2));
            __nv_bfloat16 l3 = __float2bfloat16(v3 - __bfloat162float(h3));
            *reinterpret_cast<__nv_bfloat162*>(sXhi + row * KP2 + col)       = __halves2bfloat162(h0, h1);
            *reinterpret_cast<__nv_bfloat162*>(sXlo + row * KP2 + col)       = __halves2bfloat162(l0, l1);
            *reinterpret_cast<__nv_bfloat162*>(sXhi + (row + 8) * KP2 + col) = __halves2bfloat162(h2, h3);
            *reinterpret_cast<__nv_bfloat162*>(sXlo + (row + 8) * KP2 + col) = __halves2bfloat162(l2, l3);
            acc[i][j][0] = acc[i][j][1] = acc[i][j][2] = acc[i][j][3] = 0.f;
        }
    }

    // load + split W2 (overwrites W1 tile)
    #pragma unroll
    for (int it = 0; it < 8; it++) {
        const int i   = tid + it * NT;
        const int row = i >> 5;
        const int c4  = (i & 31) * 4;
        split_store(sWhi, sWlo, row * KP2 + c4, *reinterpret_cast<const float4*>(W2 + row * H_ + c4));
    }
    __syncthreads();

    // ---- gemm2: m1 @ W2^T ----
    tile_mma<KP2, 128, 2>(sXhi, sXlo, sWhi, sWlo, wrow, wcol, lane, acc);
    __syncthreads();   // all warps done reading sW -> reuse as fp32 staging

    // stage relu(acc + b2) into smem [n_local][h], pad 129
    float* sOut = reinterpret_cast<float*>(sWhi);   // 128*129*4 = 66,048 B fits
    #pragma unroll
    for (int i = 0; i < 2; i++) {
        const int row = wrow + i * 16 + (lane >> 2);
        #pragma unroll
        for (int j = 0; j < 4; j++) {
            const int col = wcol + j * 8 + (lane & 3) * 2;
            const float bb0 = b2[col], bb1 = b2[col + 1];
            sOut[row * 129 + col]           = fmaxf(acc[i][j][0] + bb0, 0.f);
            sOut[row * 129 + col + 1]       = fmaxf(acc[i][j][1] + bb1, 0.f);
            sOut[(row + 8) * 129 + col]     = fmaxf(acc[i][j][2] + bb0, 0.f);
            sOut[(row + 8) * 129 + col + 1] = fmaxf(acc[i][j][3] + bb1, 0.f);
        }
    }
    __syncthreads();

    // transposed write-out: mt[b][h][n0+n]  (coalesced float4 along n)
    const int b  = blockIdx.x >> 4;           // 16 blocks per batch
    const int n0 = (blockIdx.x & 15) * 128;
    float* dst = mt + (long long)b * H_ * N_ + n0;
    #pragma unroll
    for (int it = 0; it < 8; it++) {
        const int i    = tid + it * NT;
        const int hrow = i >> 5;
        const int nc4  = (i & 31) * 4;
        float4 v = make_float4(sOut[(nc4 + 0) * 129 + hrow],
                               sOut[(nc4 + 1) * 129 + hrow],
                               sOut[(nc4 + 2) * 129 + hrow],
                               sOut[(nc4 + 3) * 129 + hrow]);
        *reinterpret_cast<float4*>(dst + (long long)hrow * N_ + nc4) = v;
    }
}

// -------- fused GRU: out = GRU(msg, h), gate GEMMs + gate math in one kernel ----
// 512 threads, CTA = 64 rows, warp tile 16x32 (MI=1). msg & h tiles resident;
// gate order r -> n_h -> n_x -> z keeps only TWO accumulator sets live (acc, rg);
// z is consumed inline in the epilogue. gx/gh never touch HBM.
// Dyn smem: 4x[64*KP2] + 2x[128*KP2] bf16 = 139,264 B.
__global__ void __launch_bounds__(NT, 1)
gru_fused(const float* __restrict__ msg, const float* __restrict__ h,
          const float* __restrict__ Wih, const float* __restrict__ Whh,
          const float* __restrict__ bih, const float* __restrict__ bhh,
          float* __restrict__ out)
{
    extern __shared__ __nv_bfloat16 s_r[];
    __nv_bfloat16* sMhi = s_r;                       // msg tile 64 x KP2
    __nv_bfloat16* sMlo = sMhi + 64 * KP2;
    __nv_bfloat16* sHhi = sMlo + 64 * KP2;           // h tile
    __nv_bfloat16* sHlo = sHhi + 64 * KP2;
    __nv_bfloat16* sWhi = sHlo + 64 * KP2;           // W gate slice 128 x KP2
    __nv_bfloat16* sWlo = sWhi + 128 * KP2;

    const int tid  = threadIdx.x;
    const int lane = tid & 31;
    const int warp = tid >> 5;
    const int wr   = (warp >> 2) * 16;   // warp row 0/16/32/48
    const int wc   = (warp & 3) * 32;    // warp col 0/32/64/96

    const long long row0 = (long long)blockIdx.x * 64;

    // load + split msg and h tiles: 64x128 fp32 each -> 2048 float4 each
    #pragma unroll
    for (int it = 0; it < 4; it++) {
        const int i   = tid + it * NT;       // 0..2047
        const int row = i >> 5;
        const int c4  = (i & 31) * 4;
        const int off = row * KP2 + c4;
        split_store(sMhi, sMlo, off, *reinterpret_cast<const float4*>(msg + (row0 + row) * H_ + c4));
        split_store(sHhi, sHlo, off, *reinterpret_cast<const float4*>(h   + (row0 + row) * H_ + c4));
    }

    // W slice loader: 128x128 fp32 -> smem split (sync before overwrite, sync after)
    auto loadW = [&](const float* __restrict__ Wslice) {
        __syncthreads();
        #pragma unroll
        for (int it = 0; it < 8; it++) {
            const int i   = tid + it * NT;
            const int row = i >> 5;
            const int c4  = (i & 31) * 4;
            split_store(sWhi, sWlo, row * KP2 + c4,
                        *reinterpret_cast<const float4*>(Wslice + row * H_ + c4));
        }
        __syncthreads();
    };

    float acc[1][4][4], rg[1][4][4];
    #pragma unroll
    for (int j = 0; j < 4; j++)
        #pragma unroll
        for (int t = 0; t < 4; t++) acc[0][j][t] = 0.f;

    // ---- r gate: acc = msg@Wih_r^T + h@Whh_r^T ----
    loadW(Wih);
    tile_mma<KP2, 128, 1>(sMhi, sMlo, sWhi, sWlo, wr, wc, lane, acc);
    loadW(Whh);
    tile_mma<KP2, 128, 1>(sHhi, sHlo, sWhi, sWlo, wr, wc, lane, acc);
    #pragma unroll
    for (int j = 0; j < 4; j++) {
        const int c = wc + j * 8 + (lane & 3) * 2;
        const float bb0 = bih[c] + bhh[c], bb1 = bih[c + 1] + bhh[c + 1];
        rg[0][j][0] = sigm(acc[0][j][0] + bb0);
        rg[0][j][1] = sigm(acc[0][j][1] + bb1);
        rg[0][j][2] = sigm(acc[0][j][2] + bb0);
        rg[0][j][3] = sigm(acc[0][j][3] + bb1);
        acc[0][j][0] = acc[0][j][1] = acc[0][j][2] = acc[0][j][3] = 0.f;
    }

    // ---- n gate, h-side: rg <- rg * (h@Whh_n^T + bhh_n) ----
    loadW(Whh + 256 * H_);
    tile_mma<KP2, 128, 1>(sHhi, sHlo, sWhi, sWlo, wr, wc, lane, acc);
    #pragma unroll
    for (int j = 0; j < 4; j++) {
        const int c = wc + j * 8 + (lane & 3) * 2;
        const float bb0 = bhh[256 + c], bb1 = bhh[256 + c + 1];
        rg[0][j][0] *= (acc[0][j][0] + bb0);
        rg[0][j][1] *= (acc[0][j][1] + bb1);
        rg[0][j][2] *= (acc[0][j][2] + bb0);
        rg[0][j][3] *= (acc[0][j][3] + bb1);
        acc[0][j][0] = acc[0][j][1] = acc[0][j][2] = acc[0][j][3] = 0.f;
    }

    // ---- n gate, x-side: rg <- tanh(msg@Wih_n^T + bih_n + rg)  (rg now holds n) ----
    loadW(Wih + 256 * H_);
    tile_mma<KP2, 128, 1>(sMhi, sMlo, sWhi, sWlo, wr, wc, lane, acc);
    #pragma unroll
    for (int j = 0; j < 4; j++) {
        const int c = wc + j * 8 + (lane & 3) * 2;
        const float bb0 = bih[256 + c], bb1 = bih[256 + c + 1];
        rg[0][j][0] = tanhf(acc[0][j][0] + bb0 + rg[0][j][0]);
        rg[0][j][1] = tanhf(acc[0][j][1] + bb1 + rg[0][j][1]);
        rg[0][j][2] = tanhf(acc[0][j][2] + bb0 + rg[0][j][2]);
        rg[0][j][3] = tanhf(acc[0][j][3] + bb1 + rg[0][j][3]);
        acc[0][j][0] = acc[0][j][1] = acc[0][j][2] = acc[0][j][3] = 0.f;
    }

    // ---- z gate (last): acc = msg@Wih_z^T + h@Whh_z^T, combined inline ----
    loadW(Wih + 128 * H_);
    tile_mma<KP2, 128, 1>(sMhi, sMlo, sWhi, sWlo, wr, wc, lane, acc);
    loadW(Whh + 128 * H_);
    tile_mma<KP2, 128, 1>(sHhi, sHlo, sWhi, sWlo, wr, wc, lane, acc);

    const int rl = wr + (lane >> 2);
    #pragma unroll
    for (int j = 0; j < 4; j++) {
        const int c = wc + j * 8 + (lane & 3) * 2;
        const float bb0 = bih[128 + c] + bhh[128 + c];
        const float bb1 = bih[128 + c + 1] + bhh[128 + c + 1];
        const float z0 = sigm(acc[0][j][0] + bb0);
        const float z1 = sigm(acc[0][j][1] + bb1);
        const float z2 = sigm(acc[0][j][2] + bb0);
        const float z3 = sigm(acc[0][j][3] + bb1);
        // reconstruct fp32 h from hi+lo split (err ~1e-5 rel)
        const float h0 = __bfloat162float(sHhi[rl * KP2 + c])           + __bfloat162float(sHlo[rl * KP2 + c]);
        const float h1 = __bfloat162float(sHhi[rl * KP2 + c + 1])       + __bfloat162float(sHlo[rl * KP2 + c + 1]);
        const float h2 = __bfloat162float(sHhi[(rl + 8) * KP2 + c])     + __bfloat162float(sHlo[(rl + 8) * KP2 + c]);
        const float h3 = __bfloat162float(sHhi[(rl + 8) * KP2 + c + 1]) + __bfloat162float(sHlo[(rl + 8) * KP2 + c + 1]);
        const float o0 = (1.f - z0) * rg[0][j][0] + z0 * h0;
        const float o1 = (1.f - z1) * rg[0][j][1] + z1 * h1;
        const float o2 = (1.f - z2) * rg[0][j][2] + z2 * h2;
        const float o3 = (1.f - z3) * rg[0][j][3] + z3 * h3;
        *reinterpret_cast<float2*>(out + (row0 + rl) * H_ + c)     = make_float2(o0, o1);
        *reinterpret_cast<float2*>(out + (row0 + rl + 8) * H_ + c) = make_float2(o2, o3);
    }
}

extern "C" void kernel_launch(void* const* d_in, const int* in_sizes, int n_in,
                              void* d_out, int out_size)
{
    const float* h   = (const float*)d_in[0];   // [8,2048,128]
    const float* A   = (const float*)d_in[1];   // [8,2048,2048]
    const float* W1  = (const float*)d_in[2];   // [128,128]
    const float* b1  = (const float*)d_in[3];   // [128]
    const float* W2  = (const float*)d_in[4];   // [128,128]
    const float* b2  = (const float*)d_in[5];   // [128]
    const float* Wih = (const float*)d_in[6];   // [384,128]
    const float* Whh = (const float*)d_in[7];   // [384,128]
    const float* bih = (const float*)d_in[8];   // [384]
    const float* bhh = (const float*)d_in[9];   // [384]
    float* out = (float*)d_out;                 // [8,2048,128]

    float *mt, *msg;
    cudaGetSymbolAddress((void**)&mt,  g_mt);
    cudaGetSymbolAddress((void**)&msg, g_msg);

    const dim3 blk(NT);
    const int SMEM_MLP  = 4 * 128 * KP2 * (int)sizeof(__nv_bfloat16);            // 139264
    const int SMEM_GRU  = (4 * 64 + 2 * 128) * KP2 * (int)sizeof(__nv_bfloat16); // 139264
    const int SMEM_GEMM = 2 * 4 * BM * KP * (int)sizeof(__nv_bfloat16);          // 81920

    cudaFuncSetAttribute(mlp_fused,    cudaFuncAttributeMaxDynamicSharedMemorySize, SMEM_MLP);
    cudaFuncSetAttribute(gru_fused,    cudaFuncAttributeMaxDynamicSharedMemorySize, SMEM_GRU);
    cudaFuncSetAttribute(gemm_nt_relu, cudaFuncAttributeMaxDynamicSharedMemorySize, SMEM_GEMM);

    // 1) fused MLP + transpose: mt[b][h][n] = relu(relu(h W1^T+b1) W2^T+b2)^T
    mlp_fused<<<dim3(R_ / 128), blk, SMEM_MLP>>>(h, W1, b1, W2, b2, mt);

    // 2) msg = relu(A_b @ m_b)  per batch: M=2048, N=128, K=2048 (NT vs mt)
    gemm_nt_relu<<<dim3(1, N_ / BM, B_), blk, SMEM_GEMM>>>(
        A,  (long long)N_ * N_, N_,
        mt, (long long)H_ * N_, N_,
        msg, (long long)N_ * H_, H_, N_);

    // 3) fused GRU: gate GEMMs + gate math + output combine
    gru_fused<<<dim3(R_ / 64), blk, SMEM_GRU>>>(msg, h, Wih, Whh, bih, bhh, out);
}

// round 16
// speedup vs baseline: 1.7854x; 1.0723x over previous
#include <cuda_runtime.h>
#include <cuda_bf16.h>
#include <stdint.h>

// Problem dims (fixed by the reference)
#define B_  8
#define N_  2048
#define H_  128
#define R_  (B_ * N_)   // 16384 total rows

// GEMM tiling
#define BM 128
#define BN 128
#define BK 32
#define KP 40           // padded K stride (bf16) for BK=32 tiles (conflict-free for ldmatrix)
#define KP2 136         // padded K stride (bf16) for K=128 resident tiles
#define NT 512          // threads per CTA (16 warps, 4 per SMSP)

// -------- scratch (__device__ globals: no allocation allowed) --------
__device__ float g_mt [B_ * H_ * N_];   // 8 MB   (m2 transposed per batch: [b][h][n])
__device__ float g_msg[R_ * H_];        // 8 MB

__device__ __forceinline__ uint32_t smem_u32(const void* p) {
    uint32_t a;
    asm("{ .reg .u64 t; cvta.to.shared.u64 t, %1; cvt.u32.u64 %0, t; }" : "=r"(a) : "l"(p));
    return a;
}
__device__ __forceinline__ float sigm(float x) { return 1.f / (1.f + expf(-x)); }

__device__ __forceinline__ void mma_bf16(float* c,
                                         uint32_t a0, uint32_t a1, uint32_t a2, uint32_t a3,
                                         uint32_t b0, uint32_t b1) {
    asm volatile(
        "mma.sync.aligned.m16n8k16.row.col.f32.bf16.bf16.f32 "
        "{%0,%1,%2,%3}, {%4,%5,%6,%7}, {%8,%9}, {%0,%1,%2,%3};\n"
        : "+f"(c[0]), "+f"(c[1]), "+f"(c[2]), "+f"(c[3])
        : "r"(a0), "r"(a1), "r"(a2), "r"(a3), "r"(b0), "r"(b1));
}

__device__ __forceinline__ void ldsm_x4(uint32_t* r, uint32_t addr) {
    asm volatile("ldmatrix.sync.aligned.m8n8.x4.shared.b16 {%0,%1,%2,%3}, [%4];"
                 : "=r"(r[0]), "=r"(r[1]), "=r"(r[2]), "=r"(r[3]) : "r"(addr));
}
__device__ __forceinline__ void ldsm_x2(uint32_t* r, uint32_t addr) {
    asm volatile("ldmatrix.sync.aligned.m8n8.x2.shared.b16 {%0,%1}, [%2];"
                 : "=r"(r[0]), "=r"(r[1]) : "r"(addr));
}

// split a float4 into hi/lo bf16 and store as two bf162 pairs at smem offset `off`
__device__ __forceinline__ void split_store(__nv_bfloat16* shi, __nv_bfloat16* slo,
                                            int off, float4 v) {
    float va[4] = {v.x, v.y, v.z, v.w};
    __nv_bfloat16 hi[4], lo[4];
    #pragma unroll
    for (int q = 0; q < 4; q++) {
        hi[q] = __float2bfloat16(va[q]);
        lo[q] = __float2bfloat16(va[q] - __bfloat162float(hi[q]));
    }
    *reinterpret_cast<__nv_bfloat162*>(shi + off)     = __halves2bfloat162(hi[0], hi[1]);
    *reinterpret_cast<__nv_bfloat162*>(shi + off + 2) = __halves2bfloat162(hi[2], hi[3]);
    *reinterpret_cast<__nv_bfloat162*>(slo + off)     = __halves2bfloat162(lo[0], lo[1]);
    *reinterpret_cast<__nv_bfloat162*>(slo + off + 2) = __halves2bfloat162(lo[2], lo[3]);
}

// warp-tile MMA sweep over KC columns of hi/lo split tiles, ldmatrix fragment loads.
// A rows wrow..wrow+MI*16-1, B rows wcol..wcol+31, STRIDE = padded K (bf16 elems).
// 2-term split: hi*hi + hi*lo + lo*hi (fp32 accumulate) == fp32-grade product.
// ldmatrix lane->address mapping:
//   A (.x4): lanes 0-7 rows+0..7 @kk | 8-15 rows+8..15 @kk | 16-23 rows @kk+8 | 24-31 rows+8 @kk+8
//   B (.x2): lanes 0-7 rows n+0..7 @kk | lanes 8-15 same rows @kk+8
template<int STRIDE, int KC, int MI>
__device__ __forceinline__ void tile_mma(const __nv_bfloat16* sAhi, const __nv_bfloat16* sAlo,
                                         const __nv_bfloat16* sBhi, const __nv_bfloat16* sBlo,
                                         int wrow, int wcol, int lane,
                                         float acc[][4][4]) {
    const uint32_t aHi = smem_u32(sAhi), aLo = smem_u32(sAlo);
    const uint32_t bHi = smem_u32(sBhi), bLo = smem_u32(sBlo);
    const int l7  = lane & 7;
    const int aRow    = wrow + l7 + ((lane >> 3) & 1) * 8;  // + i*16
    const int aColOff = (lane >> 4) * 8;                    // + kk
    const int bRowOff = l7;                                 // + wcol + j*8
    const int bColOff = ((lane >> 3) & 1) * 8;              // + kk (lanes 16-31 mirror 0-15)

    #pragma unroll
    for (int kk = 0; kk < KC; kk += 16) {
        uint32_t ah[MI][4], al[MI][4];
        #pragma unroll
        for (int i = 0; i < MI; i++) {
            const uint32_t off = (uint32_t)((aRow + i * 16) * STRIDE + kk + aColOff) * 2u;
            ldsm_x4(ah[i], aHi + off);
            ldsm_x4(al[i], aLo + off);
        }
        uint32_t bh[4][2], blr[4][2];
        #pragma unroll
        for (int j = 0; j < 4; j++) {
            const uint32_t off = (uint32_t)((wcol + j * 8 + bRowOff) * STRIDE + kk + bColOff) * 2u;
            ldsm_x2(bh[j],  bHi + off);
            ldsm_x2(blr[j], bLo + off);
        }
        #pragma unroll
        for (int i = 0; i < MI; i++)
            #pragma unroll
            for (int j = 0; j < 4; j++) {
                mma_bf16(acc[i][j], ah[i][0], ah[i][1], ah[i][2], ah[i][3], bh[j][0],  bh[j][1]);
                mma_bf16(acc[i][j], ah[i][0], ah[i][1], ah[i][2], ah[i][3], blr[j][0], blr[j][1]);
                mma_bf16(acc[i][j], al[i][0], al[i][1], al[i][2], al[i][3], bh[j][0],  bh[j][1]);
            }
    }
}

// ---------------- adjacency GEMM: C = relu(A * B^T) ----------------
// 512 threads, 16 warps (4x4), warp tile 32x32. Double-buffered smem; register
// prefetch of next k-tile overlaps the MMA sweep. Dyn smem 81,920 B.
__global__ void __launch_bounds__(NT, 1)
gemm_nt_relu(const float* __restrict__ A, long long strideA, int lda,
             const float* __restrict__ Bm, long long strideB, int ldb,
             float* __restrict__ C, long long strideC, int ldc,
             int K)
{
    extern __shared__ __nv_bfloat16 s_g[];

    const int tid  = threadIdx.x;
    const int lane = tid & 31;
    const int warp = tid >> 5;
    const int wrow = (warp >> 2) * 32;
    const int wcol = (warp & 3) * 32;

    const long long bz = blockIdx.z;
    const float* Ag = A  + bz * strideA + (long long)blockIdx.y * BM * lda;
    const float* Bg = Bm + bz * strideB + (long long)blockIdx.x * BN * ldb;

    const int lr = tid >> 3;         // row 0..63 (+64)
    const int lc = (tid & 7) * 4;    // float col 0..28

    float acc[2][4][4];
    #pragma unroll
    for (int i = 0; i < 2; i++)
        #pragma unroll
        for (int j = 0; j < 4; j++)
            #pragma unroll
            for (int t = 0; t < 4; t++) acc[i][j][t] = 0.f;

    // prologue: first k-tile -> buf0
    float4 ra[2], rb[2];
    #pragma unroll
    for (int p = 0; p < 2; p++) {
        ra[p] = *reinterpret_cast<const float4*>(Ag + (long long)(lr + 64 * p) * lda + lc);
        rb[p] = *reinterpret_cast<const float4*>(Bg + (long long)(lr + 64 * p) * ldb + lc);
    }
    {
        __nv_bfloat16* b0 = s_g;
        #pragma unroll
        for (int p = 0; p < 2; p++) {
            const int off = (lr + 64 * p) * KP + lc;
            split_store(b0,               b0 + BM * KP,     off, ra[p]);
            split_store(b0 + 2 * BM * KP, b0 + 3 * BM * KP, off, rb[p]);
        }
    }
    __syncthreads();

    const int nIt = K / BK;
    for (int it = 0; it < nIt; ++it) {
        const bool more = (it + 1) < nIt;
        if (more) {
            const int kn = (it + 1) * BK;
            #pragma unroll
            for (int p = 0; p < 2; p++) {
                ra[p] = *reinterpret_cast<const float4*>(Ag + (long long)(lr + 64 * p) * lda + (kn + lc));
                rb[p] = *reinterpret_cast<const float4*>(Bg + (long long)(lr + 64 * p) * ldb + (kn + lc));
            }
        }
        __nv_bfloat16* cb = s_g + (it & 1) * 4 * BM * KP;
        tile_mma<KP, BK, 2>(cb, cb + BM * KP, cb + 2 * BM * KP, cb + 3 * BM * KP,
                            wrow, wcol, lane, acc);
        if (more) {
            __nv_bfloat16* nb = s_g + ((it + 1) & 1) * 4 * BM * KP;
            #pragma unroll
            for (int p = 0; p < 2; p++) {
                const int off = (lr + 64 * p) * KP + lc;
                split_store(nb,               nb + BM * KP,     off, ra[p]);
                split_store(nb + 2 * BM * KP, nb + 3 * BM * KP, off, rb[p]);
            }
            __syncthreads();
        }
    }

    // epilogue: relu, fp32 store
    float* Cg = C + bz * strideC;
    const int rb0 = blockIdx.y * BM + wrow;
    const int cb0 = blockIdx.x * BN + wcol;
    #pragma unroll
    for (int i = 0; i < 2; i++) {
        const int r0 = rb0 + i * 16 + (lane >> 2);
        #pragma unroll
        for (int j = 0; j < 4; j++) {
            const int c0 = cb0 + j * 8 + (lane & 3) * 2;
            float v0 = fmaxf(acc[i][j][0], 0.f), v1 = fmaxf(acc[i][j][1], 0.f);
            float v2 = fmaxf(acc[i][j][2], 0.f), v3 = fmaxf(acc[i][j][3], 0.f);
            *reinterpret_cast<float2*>(Cg + (long long)r0 * ldc + c0)       = make_float2(v0, v1);
            *reinterpret_cast<float2*>(Cg + (long long)(r0 + 8) * ldc + c0) = make_float2(v2, v3);
        }
    }
}

// -------- fused MLP: mt = transpose(relu(relu(h W1^T + b1) W2^T + b2)) --------
// 512 threads, warp tile 32x32. One CTA per 128 rows; K=128 resident in smem;
// m1 never touches HBM; output staged in smem and written TRANSPOSED.
__global__ void __launch_bounds__(NT, 1)
mlp_fused(const float* __restrict__ h,
          const float* __restrict__ W1, const float* __restrict__ b1,
          const float* __restrict__ W2, const float* __restrict__ b2,
          float* __restrict__ mt)
{
    extern __shared__ __nv_bfloat16 s_m[];
    __nv_bfloat16* sXhi = s_m;
    __nv_bfloat16* sXlo = sXhi + 128 * KP2;
    __nv_bfloat16* sWhi = sXlo + 128 * KP2;
    __nv_bfloat16* sWlo = sWhi + 128 * KP2;

    const int tid  = threadIdx.x;
    const int lane = tid & 31;
    const int warp = tid >> 5;
    const int wrow = (warp >> 2) * 32;
    const int wcol = (warp & 3) * 32;

    const float* Xg = h + (long long)blockIdx.x * 128 * H_;

    #pragma unroll
    for (int it = 0; it < 8; it++) {
        const int i   = tid + it * NT;
        const int row = i >> 5;
        const int c4  = (i & 31) * 4;
        const int off = row * KP2 + c4;
        split_store(sXhi, sXlo, off, *reinterpret_cast<const float4*>(Xg + row * H_ + c4));
        split_store(sWhi, sWlo, off, *reinterpret_cast<const float4*>(W1 + row * H_ + c4));
    }
    __syncthreads();

    float acc[2][4][4];
    #pragma unroll
    for (int i = 0; i < 2; i++)
        #pragma unroll
        for (int j = 0; j < 4; j++)
            #pragma unroll
            for (int t = 0; t < 4; t++) acc[i][j][t] = 0.f;

    tile_mma<KP2, 128, 2>(sXhi, sXlo, sWhi, sWlo, wrow, wcol, lane, acc);
    __syncthreads();

    #pragma unroll
    for (int i = 0; i < 2; i++) {
        const int row = wrow + i * 16 + (lane >> 2);
        #pragma unroll
        for (int j = 0; j < 4; j++) {
            const int col = wcol + j * 8 + (lane & 3) * 2;
            const float bb0 = b1[col], bb1 = b1[col + 1];
            float v0 = fmaxf(acc[i][j][0] + bb0, 0.f);
            float v1 = fmaxf(acc[i][j][1] + bb1, 0.f);
            float v2 = fmaxf(acc[i][j][2] + bb0, 0.f);
            float v3 = fmaxf(acc[i][j][3] + bb1, 0.f);
            __nv_bfloat16 h0 = __float2bfloat16(v0), h1 = __float2bfloat16(v1);
            __nv_bfloat16 h2 = __float2bfloat16(v2), h3 = __float2bfloat16(v3);
            __nv_bfloat16 l0 = __float2bfloat16(v0 - __bfloat162float(h0));
            __nv_bfloat16 l1 = __float2bfloat16(v1 - __bfloat162float(h1));
            __nv_bfloat16 l2 = __float2bfloat16(v2 - __bfloat162float(h2));
            __nv_bfloat16 l3 = __float2bfloat16(v3 - __bfloat162float(h3));
            *reinterpret_cast<__nv_bfloat162*>(sXhi + row * KP2 + col)       = __halves2bfloat162(h0, h1);
            *reinterpret_cast<__nv_bfloat162*>(sXlo + row * KP2 + col)       = __halves2bfloat162(l0, l1);
            *reinterpret_cast<__nv_bfloat162*>(sXhi + (row + 8) * KP2 + col) = __halves2bfloat162(h2, h3);
            *reinterpret_cast<__nv_bfloat162*>(sXlo + (row + 8) * KP2 + col) = __halves2bfloat162(l2, l3);
            acc[i][j][0] = acc[i][j][1] = acc[i][j][2] = acc[i][j][3] = 0.f;
        }
    }

    #pragma unroll
    for (int it = 0; it < 8; it++) {
        const int i   = tid + it * NT;
        const int row = i >> 5;
        const int c4  = (i & 31) * 4;
        split_store(sWhi, sWlo, row * KP2 + c4, *reinterpret_cast<const float4*>(W2 + row * H_ + c4));
    }
    __syncthreads();

    tile_mma<KP2, 128, 2>(sXhi, sXlo, sWhi, sWlo, wrow, wcol, lane, acc);
    __syncthreads();

    float* sOut = reinterpret_cast<float*>(sWhi);
    #pragma unroll
    for (int i = 0; i < 2; i++) {
        const int row = wrow + i * 16 + (lane >> 2);
        #pragma unroll
        for (int j = 0; j < 4; j++) {
            const int col = wcol + j * 8 + (lane & 3) * 2;
            const float bb0 = b2[col], bb1 = b2[col + 1];
            sOut[row * 129 + col]           = fmaxf(acc[i][j][0] + bb0, 0.f);
            sOut[row * 129 + col + 1]       = fmaxf(acc[i][j][1] + bb1, 0.f);
            sOut[(row + 8) * 129 + col]     = fmaxf(acc[i][j][2] + bb0, 0.f);
            sOut[(row + 8) * 129 + col + 1] = fmaxf(acc[i][j][3] + bb1, 0.f);
        }
    }
    __syncthreads();

    const int b  = blockIdx.x >> 4;
    const int n0 = (blockIdx.x & 15) * 128;
    float* dst = mt + (long long)b * H_ * N_ + n0;
    #pragma unroll
    for (int it = 0; it < 8; it++) {
        const int i    = tid + it * NT;
        const int hrow = i >> 5;
        const int nc4  = (i & 31) * 4;
        float4 v = make_float4(sOut[(nc4 + 0) * 129 + hrow],
                               sOut[(nc4 + 1) * 129 + hrow],
                               sOut[(nc4 + 2) * 129 + hrow],
                               sOut[(nc4 + 3) * 129 + hrow]);
        *reinterpret_cast<float4*>(dst + (long long)hrow * N_ + nc4) = v;
    }
}

// -------- fused GRU: out = GRU(msg, h), gate GEMMs + gate math in one kernel ----
// 512 threads, CTA = 64 rows, warp tile 16x32 (MI=1). Gate order r -> n_h -> n_x -> z
// keeps only TWO live accumulator sets. gx/gh never touch HBM.
__global__ void __launch_bounds__(NT, 1)
gru_fused(const float* __restrict__ msg, const float* __restrict__ h,
          const float* __restrict__ Wih, const float* __restrict__ Whh,
          const float* __restrict__ bih, const float* __restrict__ bhh,
          float* __restrict__ out)
{
    extern __shared__ __nv_bfloat16 s_r[];
    __nv_bfloat16* sMhi = s_r;
    __nv_bfloat16* sMlo = sMhi + 64 * KP2;
    __nv_bfloat16* sHhi = sMlo + 64 * KP2;
    __nv_bfloat16* sHlo = sHhi + 64 * KP2;
    __nv_bfloat16* sWhi = sHlo + 64 * KP2;
    __nv_bfloat16* sWlo = sWhi + 128 * KP2;

    const int tid  = threadIdx.x;
    const int lane = tid & 31;
    const int warp = tid >> 5;
    const int wr   = (warp >> 2) * 16;
    const int wc   = (warp & 3) * 32;

    const long long row0 = (long long)blockIdx.x * 64;

    #pragma unroll
    for (int it = 0; it < 4; it++) {
        const int i   = tid + it * NT;
        const int row = i >> 5;
        const int c4  = (i & 31) * 4;
        const int off = row * KP2 + c4;
        split_store(sMhi, sMlo, off, *reinterpret_cast<const float4*>(msg + (row0 + row) * H_ + c4));
        split_store(sHhi, sHlo, off, *reinterpret_cast<const float4*>(h   + (row0 + row) * H_ + c4));
    }

    auto loadW = [&](const float* __restrict__ Wslice) {
        __syncthreads();
        #pragma unroll
        for (int it = 0; it < 8; it++) {
            const int i   = tid + it * NT;
            const int row = i >> 5;
            const int c4  = (i & 31) * 4;
            split_store(sWhi, sWlo, row * KP2 + c4,
                        *reinterpret_cast<const float4*>(Wslice + row * H_ + c4));
        }
        __syncthreads();
    };

    float acc[1][4][4], rg[1][4][4];
    #pragma unroll
    for (int j = 0; j < 4; j++)
        #pragma unroll
        for (int t = 0; t < 4; t++) acc[0][j][t] = 0.f;

    // r gate: acc = msg@Wih_r^T + h@Whh_r^T
    loadW(Wih);
    tile_mma<KP2, 128, 1>(sMhi, sMlo, sWhi, sWlo, wr, wc, lane, acc);
    loadW(Whh);
    tile_mma<KP2, 128, 1>(sHhi, sHlo, sWhi, sWlo, wr, wc, lane, acc);
    #pragma unroll
    for (int j = 0; j < 4; j++) {
        const int c = wc + j * 8 + (lane & 3) * 2;
        const float bb0 = bih[c] + bhh[c], bb1 = bih[c + 1] + bhh[c + 1];
        rg[0][j][0] = sigm(acc[0][j][0] + bb0);
        rg[0][j][1] = sigm(acc[0][j][1] + bb1);
        rg[0][j][2] = sigm(acc[0][j][2] + bb0);
        rg[0][j][3] = sigm(acc[0][j][3] + bb1);
        acc[0][j][0] = acc[0][j][1] = acc[0][j][2] = acc[0][j][3] = 0.f;
    }

    // n gate, h-side: rg <- rg * (h@Whh_n^T + bhh_n)
    loadW(Whh + 256 * H_);
    tile_mma<KP2, 128, 1>(sHhi, sHlo, sWhi, sWlo, wr, wc, lane, acc);
    #pragma unroll
    for (int j = 0; j < 4; j++) {
        const int c = wc + j * 8 + (lane & 3) * 2;
        const float bb0 = bhh[256 + c], bb1 = bhh[256 + c + 1];
        rg[0][j][0] *= (acc[0][j][0] + bb0);
        rg[0][j][1] *= (acc[0][j][1] + bb1);
        rg[0][j][2] *= (acc[0][j][2] + bb0);
        rg[0][j][3] *= (acc[0][j][3] + bb1);
        acc[0][j][0] = acc[0][j][1] = acc[0][j][2] = acc[0][j][3] = 0.f;
    }

    // n gate, x-side: rg <- tanh(msg@Wih_n^T + bih_n + rg)
    loadW(Wih + 256 * H_);
    tile_mma<KP2, 128, 1>(sMhi, sMlo, sWhi, sWlo, wr, wc, lane, acc);
    #pragma unroll
    for (int j = 0; j < 4; j++) {
        const int c = wc + j * 8 + (lane & 3) * 2;
        const float bb0 = bih[256 + c], bb1 = bih[256 + c + 1];
        rg[0][j][0] = tanhf(acc[0][j][0] + bb0 + rg[0][j][0]);
        rg[0][j][1] = tanhf(acc[0][j][1] + bb1 + rg[0][j][1]);
        rg[0][j][2] = tanhf(acc[0][j][2] + bb0 + rg[0][j][2]);
        rg[0][j][3] = tanhf(acc[0][j][3] + bb1 + rg[0][j][3]);
        acc[0][j][0] = acc[0][j][1] = acc[0][j][2] = acc[0][j][3] = 0.f;
    }

    // z gate (last), combined inline
    loadW(Wih + 128 * H_);
    tile_mma<KP2, 128, 1>(sMhi, sMlo, sWhi, sWlo, wr, wc, lane, acc);
    loadW(Whh + 128 * H_);
    tile_mma<KP2, 128, 1>(sHhi, sHlo, sWhi, sWlo, wr, wc, lane, acc);

    const int rl = wr + (lane >> 2);
    #pragma unroll
    for (int j = 0; j < 4; j++) {
        const int c = wc + j * 8 + (lane & 3) * 2;
        const float bb0 = bih[128 + c] + bhh[128 + c];
        const float bb1 = bih[128 + c + 1] + bhh[128 + c + 1];
        const float z0 = sigm(acc[0][j][0] + bb0);
        const float z1 = sigm(acc[0][j][1] + bb1);
        const float z2 = sigm(acc[0][j][2] + bb0);
        const float z3 = sigm(acc[0][j][3] + bb1);
        const float h0 = __bfloat162float(sHhi[rl * KP2 + c])           + __bfloat162float(sHlo[rl * KP2 + c]);
        const float h1 = __bfloat162float(sHhi[rl * KP2 + c + 1])       + __bfloat162float(sHlo[rl * KP2 + c + 1]);
        const float h2 = __bfloat162float(sHhi[(rl + 8) * KP2 + c])     + __bfloat162float(sHlo[(rl + 8) * KP2 + c]);
        const float h3 = __bfloat162float(sHhi[(rl + 8) * KP2 + c + 1]) + __bfloat162float(sHlo[(rl + 8) * KP2 + c + 1]);
        const float o0 = (1.f - z0) * rg[0][j][0] + z0 * h0;
        const float o1 = (1.f - z1) * rg[0][j][1] + z1 * h1;
        const float o2 = (1.f - z2) * rg[0][j][2] + z2 * h2;
        const float o3 = (1.f - z3) * rg[0][j][3] + z3 * h3;
        *reinterpret_cast<float2*>(out + (row0 + rl) * H_ + c)     = make_float2(o0, o1);
        *reinterpret_cast<float2*>(out + (row0 + rl + 8) * H_ + c) = make_float2(o2, o3);
    }
}

extern "C" void kernel_launch(void* const* d_in, const int* in_sizes, int n_in,
                              void* d_out, int out_size)
{
    const float* h   = (const float*)d_in[0];   // [8,2048,128]
    const float* A   = (const float*)d_in[1];   // [8,2048,2048]
    const float* W1  = (const float*)d_in[2];   // [128,128]
    const float* b1  = (const float*)d_in[3];   // [128]
    const float* W2  = (const float*)d_in[4];   // [128,128]
    const float* b2  = (const float*)d_in[5];   // [128]
    const float* Wih = (const float*)d_in[6];   // [384,128]
    const float* Whh = (const float*)d_in[7];   // [384,128]
    const float* bih = (const float*)d_in[8];   // [384]
    const float* bhh = (const float*)d_in[9];   // [384]
    float* out = (float*)d_out;                 // [8,2048,128]

    float *mt, *msg;
    cudaGetSymbolAddress((void**)&mt,  g_mt);
    cudaGetSymbolAddress((void**)&msg, g_msg);

    const dim3 blk(NT);
    const int SMEM_MLP  = 4 * 128 * KP2 * (int)sizeof(__nv_bfloat16);            // 139264
    const int SMEM_GRU  = (4 * 64 + 2 * 128) * KP2 * (int)sizeof(__nv_bfloat16); // 139264
    const int SMEM_GEMM = 2 * 4 * BM * KP * (int)sizeof(__nv_bfloat16);          // 81920

    cudaFuncSetAttribute(mlp_fused,    cudaFuncAttributeMaxDynamicSharedMemorySize, SMEM_MLP);
    cudaFuncSetAttribute(gru_fused,    cudaFuncAttributeMaxDynamicSharedMemorySize, SMEM_GRU);
    cudaFuncSetAttribute(gemm_nt_relu, cudaFuncAttributeMaxDynamicSharedMemorySize, SMEM_GEMM);

    // 1) fused MLP + transpose: mt[b][h][n] = relu(relu(h W1^T+b1) W2^T+b2)^T
    mlp_fused<<<dim3(R_ / 128), blk, SMEM_MLP>>>(h, W1, b1, W2, b2, mt);

    // 2) msg = relu(A_b @ m_b)  per batch: M=2048, N=128, K=2048 (NT vs mt)
    gemm_nt_relu<<<dim3(1, N_ / BM, B_), blk, SMEM_GEMM>>>(
        A,  (long long)N_ * N_, N_,
        mt, (long long)H_ * N_, N_,
        msg, (long long)N_ * H_, H_, N_);

    // 3) fused GRU: gate GEMMs + gate math + output combine
    gru_fused<<<dim3(R_ / 64), blk, SMEM_GRU>>>(msg, h, Wih, Whh, bih, bhh, out);
}

// round 17
// speedup vs baseline: 1.8395x; 1.0303x over previous
#include <cuda_runtime.h>
#include <cuda_bf16.h>
#include <stdint.h>

// Problem dims (fixed by the reference)
#define B_  8
#define N_  2048
#define H_  128
#define R_  (B_ * N_)   // 16384 total rows

// GEMM tiling
#define BM 128
#define BN 128
#define BKA 64          // adjacency K-tile
#define KPA 72          // padded K stride (bf16) for BKA tiles (conflict-free for ldmatrix)
#define KP2 136         // padded K stride (bf16) for K=128 resident tiles
#define NT 512          // threads per CTA (16 warps, 4 per SMSP)
#define ADJ_TILE (128 * KPA)   // elems per split array per buffer

// -------- scratch (__device__ globals: no allocation allowed) --------
// pre-split bf16 pairs: value = hi + lo reconstructs fp32 to ~2^-17 rel
__device__ __nv_bfloat16 g_mtHi [B_ * H_ * N_];   // 4 MB  (m2^T per batch: [b][h][n])
__device__ __nv_bfloat16 g_mtLo [B_ * H_ * N_];   // 4 MB
__device__ __nv_bfloat16 g_msgHi[R_ * H_];        // 4 MB
__device__ __nv_bfloat16 g_msgLo[R_ * H_];        // 4 MB

__device__ __forceinline__ uint32_t smem_u32(const void* p) {
    uint32_t a;
    asm("{ .reg .u64 t; cvta.to.shared.u64 t, %1; cvt.u32.u64 %0, t; }" : "=r"(a) : "l"(p));
    return a;
}
__device__ __forceinline__ float sigm(float x) { return 1.f / (1.f + expf(-x)); }

__device__ __forceinline__ void mma_bf16(float* c,
                                         uint32_t a0, uint32_t a1, uint32_t a2, uint32_t a3,
                                         uint32_t b0, uint32_t b1) {
    asm volatile(
        "mma.sync.aligned.m16n8k16.row.col.f32.bf16.bf16.f32 "
        "{%0,%1,%2,%3}, {%4,%5,%6,%7}, {%8,%9}, {%0,%1,%2,%3};\n"
        : "+f"(c[0]), "+f"(c[1]), "+f"(c[2]), "+f"(c[3])
        : "r"(a0), "r"(a1), "r"(a2), "r"(a3), "r"(b0), "r"(b1));
}
__device__ __forceinline__ void ldsm_x4(uint32_t* r, uint32_t addr) {
    asm volatile("ldmatrix.sync.aligned.m8n8.x4.shared.b16 {%0,%1,%2,%3}, [%4];"
                 : "=r"(r[0]), "=r"(r[1]), "=r"(r[2]), "=r"(r[3]) : "r"(addr));
}

__device__ __forceinline__ uint32_t pack_bf162(__nv_bfloat16 a, __nv_bfloat16 b) {
    __nv_bfloat162 p = __halves2bfloat162(a, b);
    return *reinterpret_cast<uint32_t*>(&p);
}

// split a float4 into hi/lo bf16; one 8B store per array (off must be mult of 4 elems)
__device__ __forceinline__ void split_store(__nv_bfloat16* shi, __nv_bfloat16* slo,
                                            int off, float4 v) {
    __nv_bfloat16 h0 = __float2bfloat16(v.x), h1 = __float2bfloat16(v.y);
    __nv_bfloat16 h2 = __float2bfloat16(v.z), h3 = __float2bfloat16(v.w);
    __nv_bfloat16 l0 = __float2bfloat16(v.x - __bfloat162float(h0));
    __nv_bfloat16 l1 = __float2bfloat16(v.y - __bfloat162float(h1));
    __nv_bfloat16 l2 = __float2bfloat16(v.z - __bfloat162float(h2));
    __nv_bfloat16 l3 = __float2bfloat16(v.w - __bfloat162float(h3));
    *reinterpret_cast<uint2*>(shi + off) = make_uint2(pack_bf162(h0, h1), pack_bf162(h2, h3));
    *reinterpret_cast<uint2*>(slo + off) = make_uint2(pack_bf162(l0, l1), pack_bf162(l2, l3));
}

// warp-tile MMA sweep; A fragments via 2x ldsm.x4 (hi/lo), B fragments via ONE
// combined ldsm.x4 (lanes 0-15 address sBhi, lanes 16-31 sBlo -> r0,1=bh r2,3=bl).
// 2-term split: hi*hi + hi*lo + lo*hi (fp32 accumulate) == fp32-grade product.
template<int STRIDE, int KC, int MI>
__device__ __forceinline__ void tile_mma(const __nv_bfloat16* sAhi, const __nv_bfloat16* sAlo,
                                         const __nv_bfloat16* sBhi, const __nv_bfloat16* sBlo,
                                         int wrow, int wcol, int lane,
                                         float acc[][4][4]) {
    const uint32_t aHi = smem_u32(sAhi), aLo = smem_u32(sAlo);
    const uint32_t bSel = (lane & 16) ? smem_u32(sBlo) : smem_u32(sBhi);
    const int l7   = lane & 7;
    const int aRow = wrow + l7 + ((lane >> 3) & 1) * 8;   // + i*16
    const int aCol = (lane >> 4) * 8;                     // + kk
    const int bCol = ((lane >> 3) & 1) * 8;               // + kk (pattern repeats for hi/lo halves)

    #pragma unroll
    for (int kk = 0; kk < KC; kk += 16) {
        uint32_t ah[MI][4], al[MI][4];
        #pragma unroll
        for (int i = 0; i < MI; i++) {
            const uint32_t off = (uint32_t)((aRow + i * 16) * STRIDE + kk + aCol) * 2u;
            ldsm_x4(ah[i], aHi + off);
            ldsm_x4(al[i], aLo + off);
        }
        uint32_t bb[4][4];
        #pragma unroll
        for (int j = 0; j < 4; j++) {
            const uint32_t off = (uint32_t)((wcol + j * 8 + l7) * STRIDE + kk + bCol) * 2u;
            ldsm_x4(bb[j], bSel + off);
        }
        #pragma unroll
        for (int i = 0; i < MI; i++)
            #pragma unroll
            for (int j = 0; j < 4; j++) {
                mma_bf16(acc[i][j], ah[i][0], ah[i][1], ah[i][2], ah[i][3], bb[j][0], bb[j][1]);
                mma_bf16(acc[i][j], ah[i][0], ah[i][1], ah[i][2], ah[i][3], bb[j][2], bb[j][3]);
                mma_bf16(acc[i][j], al[i][0], al[i][1], al[i][2], al[i][3], bb[j][0], bb[j][1]);
            }
    }
}

// ---------------- adjacency GEMM: msg = relu(A @ mt^T), pre-split B ----------------
// 512 threads, 16 warps (4x4), warp tile 32x32, BK=64 (KPA=72), double-buffered.
// A loaded fp32 + split on the fly; B loaded as pre-split bf16 (no conversion).
// Output written as pre-split bf16 hi/lo for the GRU kernel.
// Dyn smem: 2 buffers x 4 arrays x 128*KPA bf16 = 147,456 B.
__global__ void __launch_bounds__(NT, 1)
adj_gemm(const float* __restrict__ A,
         const __nv_bfloat16* __restrict__ mtHi, const __nv_bfloat16* __restrict__ mtLo,
         __nv_bfloat16* __restrict__ msgHi, __nv_bfloat16* __restrict__ msgLo)
{
    extern __shared__ __nv_bfloat16 s_g[];

    const int tid  = threadIdx.x;
    const int lane = tid & 31;
    const int warp = tid >> 5;
    const int wrow = (warp >> 2) * 32;
    const int wcol = (warp & 3) * 32;

    const int b  = blockIdx.z;
    const int n0 = blockIdx.y * BM;
    const float* Ab = A + (long long)b * N_ * N_ + (long long)n0 * N_;
    const __nv_bfloat16* BHi = mtHi + (long long)b * H_ * N_;
    const __nv_bfloat16* BLo = mtLo + (long long)b * H_ * N_;

    float acc[2][4][4];
    #pragma unroll
    for (int i = 0; i < 2; i++)
        #pragma unroll
        for (int j = 0; j < 4; j++)
            #pragma unroll
            for (int t = 0; t < 4; t++) acc[i][j][t] = 0.f;

    float4 ra[4];        // A: 128x64 fp32 = 2048 float4, 4/thread
    uint4  rbh[2], rbl[2]; // B: 128x64 bf16 = 1024 uint4 per array, 2/thread

    auto ldg = [&](int m0) {
        #pragma unroll
        for (int p = 0; p < 4; p++) {
            const int q = tid + p * NT;
            ra[p] = *reinterpret_cast<const float4*>(Ab + (long long)(q >> 4) * N_ + m0 + (q & 15) * 4);
        }
        #pragma unroll
        for (int p = 0; p < 2; p++) {
            const int q = tid + p * NT;
            const long long off = (long long)(q >> 3) * N_ + m0 + (q & 7) * 8;
            rbh[p] = *reinterpret_cast<const uint4*>(BHi + off);
            rbl[p] = *reinterpret_cast<const uint4*>(BLo + off);
        }
    };
    auto store_buf = [&](int buf) {
        __nv_bfloat16* base = s_g + buf * 4 * ADJ_TILE;
        #pragma unroll
        for (int p = 0; p < 4; p++) {
            const int q = tid + p * NT;
            split_store(base, base + ADJ_TILE, (q >> 4) * KPA + (q & 15) * 4, ra[p]);
        }
        #pragma unroll
        for (int p = 0; p < 2; p++) {
            const int q   = tid + p * NT;
            const int off = (q >> 3) * KPA + (q & 7) * 8;
            *reinterpret_cast<uint4*>(base + 2 * ADJ_TILE + off) = rbh[p];
            *reinterpret_cast<uint4*>(base + 3 * ADJ_TILE + off) = rbl[p];
        }
    };

    ldg(0); store_buf(0); __syncthreads();

    const int nIt = N_ / BKA;   // 32 k? no: K = N_ = 2048, BKA=64 -> 32 iters? 2048/64 = 32
    for (int it = 0; it < nIt; ++it) {
        const bool more = (it + 1) < nIt;
        if (more) ldg((it + 1) * BKA);
        __nv_bfloat16* cb = s_g + (it & 1) * 4 * ADJ_TILE;
        tile_mma<KPA, BKA, 2>(cb, cb + ADJ_TILE, cb + 2 * ADJ_TILE, cb + 3 * ADJ_TILE,
                              wrow, wcol, lane, acc);
        if (more) {
            store_buf((it + 1) & 1);
            __syncthreads();
        }
    }

    // epilogue: relu, split to bf16 hi/lo
    #pragma unroll
    for (int i = 0; i < 2; i++) {
        const int r0 = n0 + wrow + i * 16 + (lane >> 2);
        #pragma unroll
        for (int j = 0; j < 4; j++) {
            const int c0 = wcol + j * 8 + (lane & 3) * 2;
            float v0 = fmaxf(acc[i][j][0], 0.f), v1 = fmaxf(acc[i][j][1], 0.f);
            float v2 = fmaxf(acc[i][j][2], 0.f), v3 = fmaxf(acc[i][j][3], 0.f);
            __nv_bfloat16 h0 = __float2bfloat16(v0), h1 = __float2bfloat16(v1);
            __nv_bfloat16 h2 = __float2bfloat16(v2), h3 = __float2bfloat16(v3);
            __nv_bfloat16 l0 = __float2bfloat16(v0 - __bfloat162float(h0));
            __nv_bfloat16 l1 = __float2bfloat16(v1 - __bfloat162float(h1));
            __nv_bfloat16 l2 = __float2bfloat16(v2 - __bfloat162float(h2));
            __nv_bfloat16 l3 = __float2bfloat16(v3 - __bfloat162float(h3));
            const long long o0 = (long long)(b * N_ + r0) * H_ + c0;
            const long long o1 = (long long)(b * N_ + r0 + 8) * H_ + c0;
            *reinterpret_cast<uint32_t*>(msgHi + o0) = pack_bf162(h0, h1);
            *reinterpret_cast<uint32_t*>(msgLo + o0) = pack_bf162(l0, l1);
            *reinterpret_cast<uint32_t*>(msgHi + o1) = pack_bf162(h2, h3);
            *reinterpret_cast<uint32_t*>(msgLo + o1) = pack_bf162(l2, l3);
        }
    }
}

// -------- fused MLP: mtHi/Lo = split(transpose(relu(relu(h W1^T + b1) W2^T + b2))) ---
__global__ void __launch_bounds__(NT, 1)
mlp_fused(const float* __restrict__ h,
          const float* __restrict__ W1, const float* __restrict__ b1,
          const float* __restrict__ W2, const float* __restrict__ b2,
          __nv_bfloat16* __restrict__ mtHi, __nv_bfloat16* __restrict__ mtLo)
{
    extern __shared__ __nv_bfloat16 s_m[];
    __nv_bfloat16* sXhi = s_m;
    __nv_bfloat16* sXlo = sXhi + 128 * KP2;
    __nv_bfloat16* sWhi = sXlo + 128 * KP2;
    __nv_bfloat16* sWlo = sWhi + 128 * KP2;

    const int tid  = threadIdx.x;
    const int lane = tid & 31;
    const int warp = tid >> 5;
    const int wrow = (warp >> 2) * 32;
    const int wcol = (warp & 3) * 32;

    const float* Xg = h + (long long)blockIdx.x * 128 * H_;

    #pragma unroll
    for (int it = 0; it < 8; it++) {
        const int i   = tid + it * NT;
        const int row = i >> 5;
        const int c4  = (i & 31) * 4;
        const int off = row * KP2 + c4;
        split_store(sXhi, sXlo, off, *reinterpret_cast<const float4*>(Xg + row * H_ + c4));
        split_store(sWhi, sWlo, off, *reinterpret_cast<const float4*>(W1 + row * H_ + c4));
    }
    __syncthreads();

    float acc[2][4][4];
    #pragma unroll
    for (int i = 0; i < 2; i++)
        #pragma unroll
        for (int j = 0; j < 4; j++)
            #pragma unroll
            for (int t = 0; t < 4; t++) acc[i][j][t] = 0.f;

    tile_mma<KP2, 128, 2>(sXhi, sXlo, sWhi, sWlo, wrow, wcol, lane, acc);
    __syncthreads();

    #pragma unroll
    for (int i = 0; i < 2; i++) {
        const int row = wrow + i * 16 + (lane >> 2);
        #pragma unroll
        for (int j = 0; j < 4; j++) {
            const int col = wcol + j * 8 + (lane & 3) * 2;
            const float bb0 = b1[col], bb1 = b1[col + 1];
            float v0 = fmaxf(acc[i][j][0] + bb0, 0.f);
            float v1 = fmaxf(acc[i][j][1] + bb1, 0.f);
            float v2 = fmaxf(acc[i][j][2] + bb0, 0.f);
            float v3 = fmaxf(acc[i][j][3] + bb1, 0.f);
            __nv_bfloat16 h0 = __float2bfloat16(v0), h1 = __float2bfloat16(v1);
            __nv_bfloat16 h2 = __float2bfloat16(v2), h3 = __float2bfloat16(v3);
            __nv_bfloat16 l0 = __float2bfloat16(v0 - __bfloat162float(h0));
            __nv_bfloat16 l1 = __float2bfloat16(v1 - __bfloat162float(h1));
            __nv_bfloat16 l2 = __float2bfloat16(v2 - __bfloat162float(h2));
            __nv_bfloat16 l3 = __float2bfloat16(v3 - __bfloat162float(h3));
            *reinterpret_cast<uint32_t*>(sXhi + row * KP2 + col)       = pack_bf162(h0, h1);
            *reinterpret_cast<uint32_t*>(sXlo + row * KP2 + col)       = pack_bf162(l0, l1);
            *reinterpret_cast<uint32_t*>(sXhi + (row + 8) * KP2 + col) = pack_bf162(h2, h3);
            *reinterpret_cast<uint32_t*>(sXlo + (row + 8) * KP2 + col) = pack_bf162(l2, l3);
            acc[i][j][0] = acc[i][j][1] = acc[i][j][2] = acc[i][j][3] = 0.f;
        }
    }

    #pragma unroll
    for (int it = 0; it < 8; it++) {
        const int i   = tid + it * NT;
        const int row = i >> 5;
        const int c4  = (i & 31) * 4;
        split_store(sWhi, sWlo, row * KP2 + c4, *reinterpret_cast<const float4*>(W2 + row * H_ + c4));
    }
    __syncthreads();

    tile_mma<KP2, 128, 2>(sXhi, sXlo, sWhi, sWlo, wrow, wcol, lane, acc);
    __syncthreads();   // all warps done reading sW -> reuse as fp32 staging

    float* sOut = reinterpret_cast<float*>(sWhi);   // 128*129*4 = 66,048 B fits
    #pragma unroll
    for (int i = 0; i < 2; i++) {
        const int row = wrow + i * 16 + (lane >> 2);
        #pragma unroll
        for (int j = 0; j < 4; j++) {
            const int col = wcol + j * 8 + (lane & 3) * 2;
            const float bb0 = b2[col], bb1 = b2[col + 1];
            sOut[row * 129 + col]           = fmaxf(acc[i][j][0] + bb0, 0.f);
            sOut[row * 129 + col + 1]       = fmaxf(acc[i][j][1] + bb1, 0.f);
            sOut[(row + 8) * 129 + col]     = fmaxf(acc[i][j][2] + bb0, 0.f);
            sOut[(row + 8) * 129 + col + 1] = fmaxf(acc[i][j][3] + bb1, 0.f);
        }
    }
    __syncthreads();

    // transposed, pre-split write-out: mtHi/Lo[b][h][n0+n]
    const int b  = blockIdx.x >> 4;
    const int n0 = (blockIdx.x & 15) * 128;
    __nv_bfloat16* dH = mtHi + (long long)b * H_ * N_ + n0;
    __nv_bfloat16* dL = mtLo + (long long)b * H_ * N_ + n0;
    #pragma unroll
    for (int it = 0; it < 8; it++) {
        const int i    = tid + it * NT;
        const int hrow = i >> 5;
        const int nc4  = (i & 31) * 4;
        float v0 = sOut[(nc4 + 0) * 129 + hrow];
        float v1 = sOut[(nc4 + 1) * 129 + hrow];
        float v2 = sOut[(nc4 + 2) * 129 + hrow];
        float v3 = sOut[(nc4 + 3) * 129 + hrow];
        __nv_bfloat16 h0 = __float2bfloat16(v0), h1 = __float2bfloat16(v1);
        __nv_bfloat16 h2 = __float2bfloat16(v2), h3 = __float2bfloat16(v3);
        __nv_bfloat16 l0 = __float2bfloat16(v0 - __bfloat162float(h0));
        __nv_bfloat16 l1 = __float2bfloat16(v1 - __bfloat162float(h1));
        __nv_bfloat16 l2 = __float2bfloat16(v2 - __bfloat162float(h2));
        __nv_bfloat16 l3 = __float2bfloat16(v3 - __bfloat162float(h3));
        const long long o = (long long)hrow * N_ + nc4;
        *reinterpret_cast<uint2*>(dH + o) = make_uint2(pack_bf162(h0, h1), pack_bf162(h2, h3));
        *reinterpret_cast<uint2*>(dL + o) = make_uint2(pack_bf162(l0, l1), pack_bf162(l2, l3));
    }
}

// -------- fused GRU: out = GRU(msg, h); msg arrives pre-split --------
__global__ void __launch_bounds__(NT, 1)
gru_fused(const __nv_bfloat16* __restrict__ msgHi, const __nv_bfloat16* __restrict__ msgLo,
          const float* __restrict__ h,
          const float* __restrict__ Wih, const float* __restrict__ Whh,
          const float* __restrict__ bih, const float* __restrict__ bhh,
          float* __restrict__ out)
{
    extern __shared__ __nv_bfloat16 s_r[];
    __nv_bfloat16* sMhi = s_r;
    __nv_bfloat16* sMlo = sMhi + 64 * KP2;
    __nv_bfloat16* sHhi = sMlo + 64 * KP2;
    __nv_bfloat16* sHlo = sHhi + 64 * KP2;
    __nv_bfloat16* sWhi = sHlo + 64 * KP2;
    __nv_bfloat16* sWlo = sWhi + 128 * KP2;

    const int tid  = threadIdx.x;
    const int lane = tid & 31;
    const int warp = tid >> 5;
    const int wr   = (warp >> 2) * 16;
    const int wc   = (warp & 3) * 32;

    const long long row0 = (long long)blockIdx.x * 64;

    // msg tiles: direct bf16 copy (pre-split); 64x128 bf16 = 1024 uint4 per array
    #pragma unroll
    for (int p = 0; p < 2; p++) {
        const int q    = tid + p * NT;
        const int row  = q >> 4;
        const int col8 = (q & 15) * 8;
        const long long g = (row0 + row) * H_ + col8;
        *reinterpret_cast<uint4*>(sMhi + row * KP2 + col8) = *reinterpret_cast<const uint4*>(msgHi + g);
        *reinterpret_cast<uint4*>(sMlo + row * KP2 + col8) = *reinterpret_cast<const uint4*>(msgLo + g);
    }
    // h tile: fp32 load + split (fp32 h also reconstructed in epilogue)
    #pragma unroll
    for (int it = 0; it < 4; it++) {
        const int i   = tid + it * NT;
        const int row = i >> 5;
        const int c4  = (i & 31) * 4;
        split_store(sHhi, sHlo, row * KP2 + c4,
                    *reinterpret_cast<const float4*>(h + (row0 + row) * H_ + c4));
    }

    auto loadW = [&](const float* __restrict__ Wslice) {
        __syncthreads();
        #pragma unroll
        for (int it = 0; it < 8; it++) {
            const int i   = tid + it * NT;
            const int row = i >> 5;
            const int c4  = (i & 31) * 4;
            split_store(sWhi, sWlo, row * KP2 + c4,
                        *reinterpret_cast<const float4*>(Wslice + row * H_ + c4));
        }
        __syncthreads();
    };

    float acc[1][4][4], rg[1][4][4];
    #pragma unroll
    for (int j = 0; j < 4; j++)
        #pragma unroll
        for (int t = 0; t < 4; t++) acc[0][j][t] = 0.f;

    // r gate: acc = msg@Wih_r^T + h@Whh_r^T
    loadW(Wih);
    tile_mma<KP2, 128, 1>(sMhi, sMlo, sWhi, sWlo, wr, wc, lane, acc);
    loadW(Whh);
    tile_mma<KP2, 128, 1>(sHhi, sHlo, sWhi, sWlo, wr, wc, lane, acc);
    #pragma unroll
    for (int j = 0; j < 4; j++) {
        const int c = wc + j * 8 + (lane & 3) * 2;
        const float bb0 = bih[c] + bhh[c], bb1 = bih[c + 1] + bhh[c + 1];
        rg[0][j][0] = sigm(acc[0][j][0] + bb0);
        rg[0][j][1] = sigm(acc[0][j][1] + bb1);
        rg[0][j][2] = sigm(acc[0][j][2] + bb0);
        rg[0][j][3] = sigm(acc[0][j][3] + bb1);
        acc[0][j][0] = acc[0][j][1] = acc[0][j][2] = acc[0][j][3] = 0.f;
    }

    // n gate, h-side: rg <- rg * (h@Whh_n^T + bhh_n)
    loadW(Whh + 256 * H_);
    tile_mma<KP2, 128, 1>(sHhi, sHlo, sWhi, sWlo, wr, wc, lane, acc);
    #pragma unroll
    for (int j = 0; j < 4; j++) {
        const int c = wc + j * 8 + (lane & 3) * 2;
        const float bb0 = bhh[256 + c], bb1 = bhh[256 + c + 1];
        rg[0][j][0] *= (acc[0][j][0] + bb0);
        rg[0][j][1] *= (acc[0][j][1] + bb1);
        rg[0][j][2] *= (acc[0][j][2] + bb0);
        rg[0][j][3] *= (acc[0][j][3] + bb1);
        acc[0][j][0] = acc[0][j][1] = acc[0][j][2] = acc[0][j][3] = 0.f;
    }

    // n gate, x-side: rg <- tanh(msg@Wih_n^T + bih_n + rg)
    loadW(Wih + 256 * H_);
    tile_mma<KP2, 128, 1>(sMhi, sMlo, sWhi, sWlo, wr, wc, lane, acc);
    #pragma unroll
    for (int j = 0; j < 4; j++) {
        const int c = wc + j * 8 + (lane & 3) * 2;
        const float bb0 = bih[256 + c], bb1 = bih[256 + c + 1];
        rg[0][j][0] = tanhf(acc[0][j][0] + bb0 + rg[0][j][0]);
        rg[0][j][1] = tanhf(acc[0][j][1] + bb1 + rg[0][j][1]);
        rg[0][j][2] = tanhf(acc[0][j][2] + bb0 + rg[0][j][2]);
        rg[0][j][3] = tanhf(acc[0][j][3] + bb1 + rg[0][j][3]);
        acc[0][j][0] = acc[0][j][1] = acc[0][j][2] = acc[0][j][3] = 0.f;
    }

    // z gate (last), combined inline
    loadW(Wih + 128 * H_);
    tile_mma<KP2, 128, 1>(sMhi, sMlo, sWhi, sWlo, wr, wc, lane, acc);
    loadW(Whh + 128 * H_);
    tile_mma<KP2, 128, 1>(sHhi, sHlo, sWhi, sWlo, wr, wc, lane, acc);

    const int rl = wr + (lane >> 2);
    #pragma unroll
    for (int j = 0; j < 4; j++) {
        const int c = wc + j * 8 + (lane & 3) * 2;
        const float bb0 = bih[128 + c] + bhh[128 + c];
        const float bb1 = bih[128 + c + 1] + bhh[128 + c + 1];
        const float z0 = sigm(acc[0][j][0] + bb0);
        const float z1 = sigm(acc[0][j][1] + bb1);
        const float z2 = sigm(acc[0][j][2] + bb0);
        const float z3 = sigm(acc[0][j][3] + bb1);
        const float h0 = __bfloat162float(sHhi[rl * KP2 + c])           + __bfloat162float(sHlo[rl * KP2 + c]);
        const float h1 = __bfloat162float(sHhi[rl * KP2 + c + 1])       + __bfloat162float(sHlo[rl * KP2 + c + 1]);
        const float h2 = __bfloat162float(sHhi[(rl + 8) * KP2 + c])     + __bfloat162float(sHlo[(rl + 8) * KP2 + c]);
        const float h3 = __bfloat162float(sHhi[(rl + 8) * KP2 + c + 1]) + __bfloat162float(sHlo[(rl + 8) * KP2 + c + 1]);
        const float o0 = (1.f - z0) * rg[0][j][0] + z0 * h0;
        const float o1 = (1.f - z1) * rg[0][j][1] + z1 * h1;
        const float o2 = (1.f - z2) * rg[0][j][2] + z2 * h2;
        const float o3 = (1.f - z3) * rg[0][j][3] + z3 * h3;
        *reinterpret_cast<float2*>(out + (row0 + rl) * H_ + c)     = make_float2(o0, o1);
        *reinterpret_cast<float2*>(out + (row0 + rl + 8) * H_ + c) = make_float2(o2, o3);
    }
}

extern "C" void kernel_launch(void* const* d_in, const int* in_sizes, int n_in,
                              void* d_out, int out_size)
{
    const float* h   = (const float*)d_in[0];   // [8,2048,128]
    const float* A   = (const float*)d_in[1];   // [8,2048,2048]
    const float* W1  = (const float*)d_in[2];   // [128,128]
    const float* b1  = (const float*)d_in[3];   // [128]
    const float* W2  = (const float*)d_in[4];   // [128,128]
    const float* b2  = (const float*)d_in[5];   // [128]
    const float* Wih = (const float*)d_in[6];   // [384,128]
    const float* Whh = (const float*)d_in[7];   // [384,128]
    const float* bih = (const float*)d_in[8];   // [384]
    const float* bhh = (const float*)d_in[9];   // [384]
    float* out = (float*)d_out;                 // [8,2048,128]

    __nv_bfloat16 *mtHi, *mtLo, *msgHi, *msgLo;
    cudaGetSymbolAddress((void**)&mtHi,  g_mtHi);
    cudaGetSymbolAddress((void**)&mtLo,  g_mtLo);
    cudaGetSymbolAddress((void**)&msgHi, g_msgHi);
    cudaGetSymbolAddress((void**)&msgLo, g_msgLo);

    const dim3 blk(NT);
    const int SMEM_MLP = 4 * 128 * KP2 * (int)sizeof(__nv_bfloat16);            // 139264
    const int SMEM_GRU = (4 * 64 + 2 * 128) * KP2 * (int)sizeof(__nv_bfloat16); // 139264
    const int SMEM_ADJ = 2 * 4 * ADJ_TILE * (int)sizeof(__nv_bfloat16);         // 147456

    cudaFuncSetAttribute(mlp_fused, cudaFuncAttributeMaxDynamicSharedMemorySize, SMEM_MLP);
    cudaFuncSetAttribute(gru_fused, cudaFuncAttributeMaxDynamicSharedMemorySize, SMEM_GRU);
    cudaFuncSetAttribute(adj_gemm,  cudaFuncAttributeMaxDynamicSharedMemorySize, SMEM_ADJ);

    // 1) fused MLP + transpose + split: mtHi/Lo[b][h][n]
    mlp_fused<<<dim3(R_ / 128), blk, SMEM_MLP>>>(h, W1, b1, W2, b2, mtHi, mtLo);

    // 2) msg = relu(A_b @ m_b), pre-split in/out (per batch: M=2048, N=128, K=2048)
    adj_gemm<<<dim3(1, N_ / BM, B_), blk, SMEM_ADJ>>>(A, mtHi, mtLo, msgHi, msgLo);

    // 3) fused GRU: gate GEMMs + gate math + output combine
    gru_fused<<<dim3(R_ / 64), blk, SMEM_GRU>>>(msgHi, msgLo, h, Wih, Whh, bih, bhh, out);
}